// round 10
// baseline (speedup 1.0000x reference)
#include <cuda_runtime.h>
#include <cuda_fp16.h>
#include <cstdint>

#define DIM_ 4096
#define BM 128
#define BN 128
#define BKH 32               // fp16 k per chunk (64B per row)
#define NCH (DIM_ / BKH)     // 128 chunks
#define GRP 8                // chunks per RZ-chain group (drain period, GEMM1)
#define ROWB 80              // padded smem row stride (64B data + 16B pad), ldsm conflict-free
#define TILEB (BM * ROWB)    // 10240 B per tile
#define NSTG 4

// Scales (exact powers of 2): x*2^12 -> (x0,x1); Pi*2^16 -> (p0,p1);
// y~ stored fp16(c*2^12) single; Pi^T stored fp16(Pi^T*2^16) single.
// GEMM1 acc = 2^28*y, bnd*2^27. GEMM2 acc = 2^28*x~, out *2^-28.

// ---------------- scratch (allocation-free rule: __device__ globals) --------
__device__ unsigned short g_x0[(size_t)DIM_ * DIM_];
__device__ unsigned short g_x1[(size_t)DIM_ * DIM_];
__device__ unsigned short g_p0[(size_t)DIM_ * DIM_];
__device__ unsigned short g_p1[(size_t)DIM_ * DIM_];
__device__ unsigned short g_th[(size_t)DIM_ * DIM_];   // fp16(2^16 Pi^T), K-major
__device__ unsigned short g_yh[(size_t)DIM_ * DIM_];   // fp16(2^12 y~)

// ---------------- PTX helpers -----------------------------------------------
__device__ __forceinline__ uint32_t smem_u32(const void* p) {
    uint32_t a;
    asm("{ .reg .u64 t; cvta.to.shared.u64 t, %1; cvt.u32.u64 %0, t; }" : "=r"(a) : "l"(p));
    return a;
}
__device__ __forceinline__ void cpasync16(uint32_t sa, const void* g) {
    asm volatile("cp.async.cg.shared.global [%0], [%1], 16;" :: "r"(sa), "l"(g));
}
__device__ __forceinline__ void ldsm4(uint32_t* r, uint32_t a) {
    asm volatile("ldmatrix.sync.aligned.m8n8.x4.shared.b16 {%0,%1,%2,%3}, [%4];"
                 : "=r"(r[0]), "=r"(r[1]), "=r"(r[2]), "=r"(r[3]) : "r"(a));
}
__device__ __forceinline__ void mma16816(float* d, const uint32_t* a, const uint32_t* b) {
    asm volatile("mma.sync.aligned.m16n8k16.row.col.f32.f16.f16.f32 "
                 "{%0,%1,%2,%3}, {%4,%5,%6,%7}, {%8,%9}, {%0,%1,%2,%3};"
                 : "+f"(d[0]), "+f"(d[1]), "+f"(d[2]), "+f"(d[3])
                 : "r"(a[0]), "r"(a[1]), "r"(a[2]), "r"(a[3]), "r"(b[0]), "r"(b[1]));
}
#define CP_COMMIT() asm volatile("cp.async.commit_group;" ::: "memory")
#define CP_WAIT2()  asm volatile("cp.async.wait_group 2;" ::: "memory")

// ---------------- fp16 2-split (Markidis, pre-scaled) -----------------------
__device__ __forceinline__ void hsplit2(float v, unsigned short& b0, unsigned short& b1) {
    __half h0 = __float2half_rn(v);
    float r = v - __half2float(h0);
    __half h1 = __float2half_rn(r);
    b0 = *reinterpret_cast<unsigned short*>(&h0);
    b1 = *reinterpret_cast<unsigned short*>(&h1);
}

template<int SCALE>
__global__ void split2_kernel(const float4* __restrict__ in,
                              uint32_t* __restrict__ o0, uint32_t* __restrict__ o1) {
    int i = blockIdx.x * blockDim.x + threadIdx.x;
    float4 v = in[i];
    const float s = (float)SCALE;
    unsigned short a0[4], a1[4];
    hsplit2(v.x * s, a0[0], a1[0]);
    hsplit2(v.y * s, a0[1], a1[1]);
    hsplit2(v.z * s, a0[2], a1[2]);
    hsplit2(v.w * s, a0[3], a1[3]);
    o0[2 * i] = a0[0] | ((uint32_t)a0[1] << 16); o0[2 * i + 1] = a0[2] | ((uint32_t)a0[3] << 16);
    o1[2 * i] = a1[0] | ((uint32_t)a1[1] << 16); o1[2 * i + 1] = a1[2] | ((uint32_t)a1[3] << 16);
}

// Pi -> fp16(2^16 Pi^T), tiled transpose, single value (no split)
__global__ void transhalf_kernel(const float* __restrict__ Pi,
                                 unsigned short* __restrict__ th) {
    __shared__ float tile[32][33];
    int tx = threadIdx.x, ty = threadIdx.y;
    int c0 = blockIdx.x * 32, r0 = blockIdx.y * 32;
    #pragma unroll
    for (int i = 0; i < 4; ++i)
        tile[ty + 8 * i][tx] = Pi[(size_t)(r0 + ty + 8 * i) * DIM_ + c0 + tx];
    __syncthreads();
    #pragma unroll
    for (int i = 0; i < 4; ++i) {
        __half h = __float2half_rn(tile[tx][ty + 8 * i] * 65536.0f);
        th[(size_t)(c0 + ty + 8 * i) * DIM_ + r0 + tx] = *reinterpret_cast<unsigned short*>(&h);
    }
}

// ---------------- split GEMM via mma.sync (HMMA fp16) -----------------------
// NPROD=3 (GEMM1): a0b0 + a0b1 + a1b0, 4 tiles/stage, RZ group-drain to smem,
//                  quantize epilogue -> single fp16 y~.
// NPROD=1 (GEMM2): plain a0b0, 2 tiles/stage, fp32 epilogue *2^-28.
template<int NPROD, bool QUANT>
__global__ __launch_bounds__(512, 1)
void hmma_gemm(const unsigned short* __restrict__ A0, const unsigned short* __restrict__ A1,
               const unsigned short* __restrict__ Bm0, const unsigned short* __restrict__ Bm1,
               const float* __restrict__ cb, float* __restrict__ Cout,
               unsigned short* __restrict__ Yh)
{
    constexpr int NSPL = (NPROD == 3) ? 2 : 1;   // splits per operand
    constexpr int NT = 2 * NSPL;                 // tiles per stage
    constexpr int STGB = NT * TILEB;

    extern __shared__ char smem[];
    const uint32_t sb = smem_u32(smem);
    float* s_acc = (float*)(smem + NSTG * STGB);   // [32][512] lane-major (QUANT only)
    __shared__ float s_bnd[15];        // 2^27 * (c_i + c_{i+1})
    __shared__ uint32_t s_cbh[16];     // fp16(2^12 * codebook) in low 16 bits

    const int tid = threadIdx.x;
    const int w = tid >> 5, l = tid & 31;
    const int wm = w & 3, wn = w >> 2;          // 4x4 warp grid, warp tile 32x32
    const int row0 = blockIdx.y * BM;
    const int col0 = blockIdx.x * BN;

    if (QUANT) {
        if (tid < 16) {
            __half h = __float2half_rn(cb[tid] * 4096.0f);
            s_cbh[tid] = (uint32_t)(*reinterpret_cast<unsigned short*>(&h));
        }
        if (tid < 15) s_bnd[tid] = (cb[tid] + cb[tid + 1]) * 134217728.0f;  // 2^27
        #pragma unroll
        for (int i = 0; i < 32; ++i) s_acc[i * 512 + tid] = 0.0f;  // own slots only
    }

    const unsigned short* srcs[NT];
    int rb[NT];
    srcs[0] = A0; rb[0] = row0;
    if (NSPL == 2) { srcs[1] = A1; rb[1] = row0; }
    srcs[NSPL] = Bm0; rb[NSPL] = col0;
    if (NSPL == 2) { srcs[NSPL + 1] = Bm1; rb[NSPL + 1] = col0; }

    const int cr = tid >> 2, cc = tid & 3;
    const unsigned short* gp[NT];
    #pragma unroll
    for (int t = 0; t < NT; ++t)
        gp[t] = srcs[t] + (size_t)(rb[t] + cr) * DIM_ + cc * 8;
    const uint32_t swr = cr * ROWB + cc * 16;

    auto load_chunk = [&](int ch, int st) {
        const int k0 = ch * BKH;
        const uint32_t stg = sb + st * STGB;
        #pragma unroll
        for (int t = 0; t < NT; ++t)
            cpasync16(stg + t * TILEB + swr, gp[t] + k0);
        CP_COMMIT();
    };

    float acc[2][4][4];
    #pragma unroll
    for (int f = 0; f < 2; ++f)
        #pragma unroll
        for (int j = 0; j < 4; ++j)
            #pragma unroll
            for (int q = 0; q < 4; ++q) acc[f][j][q] = 0.0f;

    const uint32_t a_off = (uint32_t)(wm * 32 + (l & 15)) * ROWB + (l >> 4) * 16;
    const uint32_t b_off = (uint32_t)(wn * 32 + (l & 7) + ((l >> 4) & 1) * 8) * ROWB
                         + ((l >> 3) & 1) * 16;

    load_chunk(0, 0);
    load_chunk(1, 1);
    load_chunk(2, 2);

    for (int t = 0; t < NCH; ++t) {
        const int st = t & 3;
        CP_WAIT2();                      // uniform commits: chunk t arrived
        __syncthreads();
        if (t + 3 < NCH) load_chunk(t + 3, (t + 3) & 3);
        else             CP_COMMIT();    // empty group keeps pending-count exact

        const uint32_t base = sb + st * STGB;
        #pragma unroll
        for (int ks = 0; ks < 2; ++ks) {
            uint32_t afr[NSPL][2][4];
            #pragma unroll
            for (int s = 0; s < NSPL; ++s)
                #pragma unroll
                for (int f = 0; f < 2; ++f)
                    ldsm4(afr[s][f], base + s * TILEB + a_off + f * 16 * ROWB + ks * 32);

            #pragma unroll
            for (int sB = 0; sB < NSPL; ++sB) {
                uint32_t bfr[2][4];
                #pragma unroll
                for (int p = 0; p < 2; ++p)
                    ldsm4(bfr[p], base + (NSPL + sB) * TILEB + b_off + p * 16 * ROWB + ks * 32);
                // sB==0: a0*b0 (+ a1*b0 when NPROD==3) ; sB==1: a0*b1
                #pragma unroll
                for (int f = 0; f < 2; ++f)
                    #pragma unroll
                    for (int j = 0; j < 4; ++j)
                        mma16816(acc[f][j], afr[0][f], &bfr[j >> 1][(j & 1) * 2]);
                if (NPROD == 3 && sB == 0) {
                    #pragma unroll
                    for (int f = 0; f < 2; ++f)
                        #pragma unroll
                        for (int j = 0; j < 4; ++j)
                            mma16816(acc[f][j], afr[1][f], &bfr[j >> 1][(j & 1) * 2]);
                }
            }
        }

        // group drain: RN-add partial into smem total, reset RZ chain
        if (QUANT && (t & (GRP - 1)) == (GRP - 1)) {
            #pragma unroll
            for (int f = 0; f < 2; ++f)
                #pragma unroll
                for (int j = 0; j < 4; ++j)
                    #pragma unroll
                    for (int q = 0; q < 4; ++q) {
                        const int i = ((f * 4 + j) * 4 + q) * 512 + tid;
                        s_acc[i] += acc[f][j][q];
                        acc[f][j][q] = 0.0f;
                    }
        }
    }

    // ---- epilogue -----------------------------------------------------------
    // element map: m = wm*32 + f*16 + (q>=2)*8 + l/4 ; n = wn*32 + j*8 + 2*(l&3) + (q&1)
    #pragma unroll
    for (int f = 0; f < 2; ++f) {
        #pragma unroll
        for (int j = 0; j < 4; ++j) {
            const int nb = col0 + wn * 32 + j * 8 + (l & 3) * 2;
            #pragma unroll
            for (int h = 0; h < 2; ++h) {
                const int row = row0 + wm * 32 + f * 16 + h * 8 + (l >> 2);
                if (QUANT) {
                    const float va = s_acc[((f * 4 + j) * 4 + 2 * h) * 512 + tid];
                    const float vb = s_acc[((f * 4 + j) * 4 + 2 * h + 1) * 512 + tid];
                    int ia = 0, ib = 0;
                    #pragma unroll
                    for (int q = 0; q < 15; ++q) {
                        ia += (va > s_bnd[q]) ? 1 : 0;
                        ib += (vb > s_bnd[q]) ? 1 : 0;
                    }
                    const size_t o = ((size_t)row * DIM_ + nb) >> 1;
                    ((uint32_t*)Yh)[o] = s_cbh[ia] | (s_cbh[ib] << 16);
                } else {
                    const float s = 1.0f / 268435456.0f;   // 2^-28
                    *(float2*)(Cout + (size_t)row * DIM_ + nb) =
                        make_float2(acc[f][j][2 * h] * s, acc[f][j][2 * h + 1] * s);
                }
            }
        }
    }
}

// ---------------- host ------------------------------------------------------
extern "C" void kernel_launch(void* const* d_in, const int* in_sizes, int n_in,
                              void* d_out, int out_size)
{
    const float* x  = (const float*)d_in[0];
    const float* Pi = (const float*)d_in[1];
    const float* cb = (const float*)d_in[2];
    float* out = (float*)d_out;

    unsigned short *x0, *x1, *p0, *p1, *th, *yh;
    cudaGetSymbolAddress((void**)&x0, g_x0);
    cudaGetSymbolAddress((void**)&x1, g_x1);
    cudaGetSymbolAddress((void**)&p0, g_p0);
    cudaGetSymbolAddress((void**)&p1, g_p1);
    cudaGetSymbolAddress((void**)&th, g_th);
    cudaGetSymbolAddress((void**)&yh, g_yh);

    const size_t N = (size_t)DIM_ * DIM_;
    const int smem1 = NSTG * 4 * TILEB + 512 * 32 * 4;   // 163840 + 65536 = 229376
    const int smem2 = NSTG * 2 * TILEB;                  // 81920
    cudaFuncSetAttribute(hmma_gemm<3, true>,
                         cudaFuncAttributeMaxDynamicSharedMemorySize, smem1);
    cudaFuncSetAttribute(hmma_gemm<1, false>,
                         cudaFuncAttributeMaxDynamicSharedMemorySize, smem2);

    // 1) prep: 2^12 x -> (x0,x1) ; 2^16 Pi -> (p0,p1) ; fp16(2^16 Pi^T) -> th
    split2_kernel<4096><<<(int)(N / 4 / 256), 256>>>((const float4*)x,
                                                     (uint32_t*)x0, (uint32_t*)x1);
    split2_kernel<65536><<<(int)(N / 4 / 256), 256>>>((const float4*)Pi,
                                                      (uint32_t*)p0, (uint32_t*)p1);
    transhalf_kernel<<<dim3(DIM_ / 32, DIM_ / 32), dim3(32, 8)>>>(Pi, th);

    dim3 grid(DIM_ / BN, DIM_ / BM);
    // 2) GEMM1 (3-product, group-drained) + quantize -> yh = fp16(2^12 y~)
    hmma_gemm<3, true><<<grid, 512, smem1>>>(x0, x1, p0, p1, cb, nullptr, yh);
    // 3) GEMM2 (single product): out = (2^12 y~ @ 2^16 Pi) * 2^-28
    hmma_gemm<1, false><<<grid, 512, smem2>>>(yh, nullptr, th, nullptr, nullptr, out, nullptr);
}

// round 11
// speedup vs baseline: 1.5301x; 1.5301x over previous
#include <cuda_runtime.h>
#include <cuda_fp16.h>
#include <cstdint>

#define DIM_ 4096
#define BM 128
#define BN 128
#define BKH 32               // fp16 k per chunk (64B per row)
#define NCH (DIM_ / BKH)     // 128 chunks
#define GRP 4                // chunks per RZ-chain group (drain period, GEMM1)
#define ROWB 80              // padded smem row stride (64B data + 16B pad), ldsm conflict-free
#define TILEB (BM * ROWB)    // 10240 B per tile
#define STGB (4 * TILEB)     // 4 tiles per stage (GEMM1: A0,A1,B0,B1)
#define NSTG 4
#define STGB2 (2 * TILEB)    // 2 tiles per stage (GEMM2: A,B)

// Scales (exact powers of 2): x*2^12 -> (x0,x1); Pi*2^16 -> (p0,p1);
// y~ stored fp16(c*2^12); Pi^T stored fp16(Pi^T*2^16).
// GEMM1 acc = 2^28*y, bnd*2^27. GEMM2 acc = 2^28*x~, out *2^-28.

// ---------------- scratch (allocation-free rule: __device__ globals) --------
__device__ unsigned short g_x0[(size_t)DIM_ * DIM_];
__device__ unsigned short g_x1[(size_t)DIM_ * DIM_];
__device__ unsigned short g_p0[(size_t)DIM_ * DIM_];
__device__ unsigned short g_p1[(size_t)DIM_ * DIM_];
__device__ unsigned short g_th[(size_t)DIM_ * DIM_];   // fp16(2^16 Pi^T), K-major
__device__ unsigned short g_yh[(size_t)DIM_ * DIM_];   // fp16(2^12 y~)

// ---------------- PTX helpers -----------------------------------------------
__device__ __forceinline__ uint32_t smem_u32(const void* p) {
    uint32_t a;
    asm("{ .reg .u64 t; cvta.to.shared.u64 t, %1; cvt.u32.u64 %0, t; }" : "=r"(a) : "l"(p));
    return a;
}
__device__ __forceinline__ void cpasync16(uint32_t sa, const void* g) {
    asm volatile("cp.async.cg.shared.global [%0], [%1], 16;" :: "r"(sa), "l"(g));
}
__device__ __forceinline__ void ldsm4(uint32_t* r, uint32_t a) {
    asm volatile("ldmatrix.sync.aligned.m8n8.x4.shared.b16 {%0,%1,%2,%3}, [%4];"
                 : "=r"(r[0]), "=r"(r[1]), "=r"(r[2]), "=r"(r[3]) : "r"(a));
}
__device__ __forceinline__ void mma16816(float* d, const uint32_t* a, const uint32_t* b) {
    asm volatile("mma.sync.aligned.m16n8k16.row.col.f32.f16.f16.f32 "
                 "{%0,%1,%2,%3}, {%4,%5,%6,%7}, {%8,%9}, {%0,%1,%2,%3};"
                 : "+f"(d[0]), "+f"(d[1]), "+f"(d[2]), "+f"(d[3])
                 : "r"(a[0]), "r"(a[1]), "r"(a[2]), "r"(a[3]), "r"(b[0]), "r"(b[1]));
}
#define CP_COMMIT() asm volatile("cp.async.commit_group;" ::: "memory")
#define CP_WAIT2()  asm volatile("cp.async.wait_group 2;" ::: "memory")

// ---------------- fp16 2-split (Markidis, pre-scaled) -----------------------
__device__ __forceinline__ void hsplit2(float v, unsigned short& b0, unsigned short& b1) {
    __half h0 = __float2half_rn(v);
    float r = v - __half2float(h0);
    __half h1 = __float2half_rn(r);
    b0 = *reinterpret_cast<unsigned short*>(&h0);
    b1 = *reinterpret_cast<unsigned short*>(&h1);
}

template<int SCALE>
__global__ void split2_kernel(const float4* __restrict__ in,
                              uint32_t* __restrict__ o0, uint32_t* __restrict__ o1) {
    int i = blockIdx.x * blockDim.x + threadIdx.x;
    float4 v = in[i];
    const float s = (float)SCALE;
    unsigned short a0[4], a1[4];
    hsplit2(v.x * s, a0[0], a1[0]);
    hsplit2(v.y * s, a0[1], a1[1]);
    hsplit2(v.z * s, a0[2], a1[2]);
    hsplit2(v.w * s, a0[3], a1[3]);
    o0[2 * i] = a0[0] | ((uint32_t)a0[1] << 16); o0[2 * i + 1] = a0[2] | ((uint32_t)a0[3] << 16);
    o1[2 * i] = a1[0] | ((uint32_t)a1[1] << 16); o1[2 * i + 1] = a1[2] | ((uint32_t)a1[3] << 16);
}

// Pi -> fp16(2^16 Pi^T), tiled transpose
__global__ void transhalf_kernel(const float* __restrict__ Pi,
                                 unsigned short* __restrict__ th) {
    __shared__ float tile[32][33];
    int tx = threadIdx.x, ty = threadIdx.y;
    int c0 = blockIdx.x * 32, r0 = blockIdx.y * 32;
    #pragma unroll
    for (int i = 0; i < 4; ++i)
        tile[ty + 8 * i][tx] = Pi[(size_t)(r0 + ty + 8 * i) * DIM_ + c0 + tx];
    __syncthreads();
    #pragma unroll
    for (int i = 0; i < 4; ++i) {
        __half h = __float2half_rn(tile[tx][ty + 8 * i] * 65536.0f);
        th[(size_t)(c0 + ty + 8 * i) * DIM_ + r0 + tx] = *reinterpret_cast<unsigned short*>(&h);
    }
}

// ---------------- GEMM1: 3-product split HMMA + quantize (R8 mainloop) ------
__global__ __launch_bounds__(512, 1)
void gemm1_kernel(const unsigned short* __restrict__ A0, const unsigned short* __restrict__ A1,
                  const unsigned short* __restrict__ Bm0, const unsigned short* __restrict__ Bm1,
                  const float* __restrict__ cb, unsigned short* __restrict__ Yh)
{
    extern __shared__ char smem[];
    const uint32_t sb = smem_u32(smem);
    float* s_acc = (float*)(smem + NSTG * STGB);   // [32][512] lane-major
    __shared__ float s_bnd[15];        // 2^27 * (c_i + c_{i+1})
    __shared__ uint32_t s_cbh[16];     // fp16(2^12 * codebook), low 16 bits

    const int tid = threadIdx.x;
    const int w = tid >> 5, l = tid & 31;
    const int wm = w & 3, wn = w >> 2;          // 4x4 warp grid, warp tile 32x32
    const int row0 = blockIdx.y * BM;
    const int col0 = blockIdx.x * BN;

    if (tid < 16) {
        __half h = __float2half_rn(cb[tid] * 4096.0f);
        s_cbh[tid] = (uint32_t)(*reinterpret_cast<unsigned short*>(&h));
    }
    if (tid < 15) s_bnd[tid] = (cb[tid] + cb[tid + 1]) * 134217728.0f;  // 2^27
    #pragma unroll
    for (int i = 0; i < 32; ++i) s_acc[i * 512 + tid] = 0.0f;  // own slots only

    const unsigned short* srcs[4] = {A0, A1, Bm0, Bm1};
    const int rb[4] = {row0, row0, col0, col0};

    const int cr = tid >> 2, cc = tid & 3;
    const unsigned short* gp[4];
    #pragma unroll
    for (int t = 0; t < 4; ++t)
        gp[t] = srcs[t] + (size_t)(rb[t] + cr) * DIM_ + cc * 8;
    const uint32_t swr = cr * ROWB + cc * 16;

    auto load_chunk = [&](int ch, int st) {
        const int k0 = ch * BKH;
        const uint32_t stg = sb + st * STGB;
        #pragma unroll
        for (int t = 0; t < 4; ++t)
            cpasync16(stg + t * TILEB + swr, gp[t] + k0);
        CP_COMMIT();
    };

    float acc[2][4][4];
    #pragma unroll
    for (int f = 0; f < 2; ++f)
        #pragma unroll
        for (int j = 0; j < 4; ++j)
            #pragma unroll
            for (int q = 0; q < 4; ++q) acc[f][j][q] = 0.0f;

    const uint32_t a_off = (uint32_t)(wm * 32 + (l & 15)) * ROWB + (l >> 4) * 16;
    const uint32_t b_off = (uint32_t)(wn * 32 + (l & 7) + ((l >> 4) & 1) * 8) * ROWB
                         + ((l >> 3) & 1) * 16;

    load_chunk(0, 0);
    load_chunk(1, 1);
    load_chunk(2, 2);

    for (int t = 0; t < NCH; ++t) {
        const int st = t & 3;
        CP_WAIT2();                      // uniform commits: chunk t arrived
        __syncthreads();
        if (t + 3 < NCH) load_chunk(t + 3, (t + 3) & 3);
        else             CP_COMMIT();    // empty group keeps pending-count exact

        const uint32_t base = sb + st * STGB;
        #pragma unroll
        for (int ks = 0; ks < 2; ++ks) {
            uint32_t afr[2][2][4];
            #pragma unroll
            for (int s = 0; s < 2; ++s)
                #pragma unroll
                for (int f = 0; f < 2; ++f)
                    ldsm4(afr[s][f], base + s * TILEB + a_off + f * 16 * ROWB + ks * 32);

            #pragma unroll
            for (int sB = 0; sB < 2; ++sB) {
                uint32_t bfr[2][4];
                #pragma unroll
                for (int p = 0; p < 2; ++p)
                    ldsm4(bfr[p], base + (2 + sB) * TILEB + b_off + p * 16 * ROWB + ks * 32);
                // sB==0: a0*b0 + a1*b0 ; sB==1: a0*b1
                #pragma unroll
                for (int f = 0; f < 2; ++f)
                    #pragma unroll
                    for (int j = 0; j < 4; ++j)
                        mma16816(acc[f][j], afr[0][f], &bfr[j >> 1][(j & 1) * 2]);
                if (sB == 0) {
                    #pragma unroll
                    for (int f = 0; f < 2; ++f)
                        #pragma unroll
                        for (int j = 0; j < 4; ++j)
                            mma16816(acc[f][j], afr[1][f], &bfr[j >> 1][(j & 1) * 2]);
                }
            }
        }

        // group drain: RN-add partial into smem total, reset RZ chain
        if ((t & (GRP - 1)) == (GRP - 1)) {
            #pragma unroll
            for (int f = 0; f < 2; ++f)
                #pragma unroll
                for (int j = 0; j < 4; ++j)
                    #pragma unroll
                    for (int q = 0; q < 4; ++q) {
                        const int i = ((f * 4 + j) * 4 + q) * 512 + tid;
                        s_acc[i] += acc[f][j][q];
                        acc[f][j][q] = 0.0f;
                    }
        }
    }

    // ---- epilogue: quantize -> single fp16 y~ -------------------------------
    #pragma unroll
    for (int f = 0; f < 2; ++f) {
        #pragma unroll
        for (int j = 0; j < 4; ++j) {
            const int nb = col0 + wn * 32 + j * 8 + (l & 3) * 2;
            #pragma unroll
            for (int h = 0; h < 2; ++h) {
                const int row = row0 + wm * 32 + f * 16 + h * 8 + (l >> 2);
                const float va = s_acc[((f * 4 + j) * 4 + 2 * h) * 512 + tid];
                const float vb = s_acc[((f * 4 + j) * 4 + 2 * h + 1) * 512 + tid];
                int ia = 0, ib = 0;
                #pragma unroll
                for (int q = 0; q < 15; ++q) {
                    ia += (va > s_bnd[q]) ? 1 : 0;
                    ib += (vb > s_bnd[q]) ? 1 : 0;
                }
                const size_t o = ((size_t)row * DIM_ + nb) >> 1;
                ((uint32_t*)Yh)[o] = s_cbh[ia] | (s_cbh[ib] << 16);
            }
        }
    }
}

// ---------------- GEMM2: plain single-product fp16 HMMA ---------------------
__global__ __launch_bounds__(512, 1)
void gemm2_kernel(const unsigned short* __restrict__ A, const unsigned short* __restrict__ B,
                  float* __restrict__ Cout)
{
    extern __shared__ char smem[];
    const uint32_t sb = smem_u32(smem);

    const int tid = threadIdx.x;
    const int w = tid >> 5, l = tid & 31;
    const int wm = w & 3, wn = w >> 2;          // 4x4 warp grid, warp tile 32x32
    const int row0 = blockIdx.y * BM;
    const int col0 = blockIdx.x * BN;

    const int cr = tid >> 2, cc = tid & 3;
    const unsigned short* gpa = A + (size_t)(row0 + cr) * DIM_ + cc * 8;
    const unsigned short* gpb = B + (size_t)(col0 + cr) * DIM_ + cc * 8;
    const uint32_t swr = cr * ROWB + cc * 16;

    auto load_chunk = [&](int ch, int st) {
        const int k0 = ch * BKH;
        const uint32_t stg = sb + st * STGB2;
        cpasync16(stg + swr, gpa + k0);
        cpasync16(stg + TILEB + swr, gpb + k0);
        CP_COMMIT();
    };

    float acc[2][4][4];
    #pragma unroll
    for (int f = 0; f < 2; ++f)
        #pragma unroll
        for (int j = 0; j < 4; ++j)
            #pragma unroll
            for (int q = 0; q < 4; ++q) acc[f][j][q] = 0.0f;

    const uint32_t a_off = (uint32_t)(wm * 32 + (l & 15)) * ROWB + (l >> 4) * 16;
    const uint32_t b_off = (uint32_t)(wn * 32 + (l & 7) + ((l >> 4) & 1) * 8) * ROWB
                         + ((l >> 3) & 1) * 16;

    load_chunk(0, 0);
    load_chunk(1, 1);
    load_chunk(2, 2);

    for (int t = 0; t < NCH; ++t) {
        const int st = t & 3;
        CP_WAIT2();
        __syncthreads();
        if (t + 3 < NCH) load_chunk(t + 3, (t + 3) & 3);
        else             CP_COMMIT();

        const uint32_t base = sb + st * STGB2;
        #pragma unroll
        for (int ks = 0; ks < 2; ++ks) {
            uint32_t afr[2][4];
            #pragma unroll
            for (int f = 0; f < 2; ++f)
                ldsm4(afr[f], base + a_off + f * 16 * ROWB + ks * 32);
            uint32_t bfr[2][4];
            #pragma unroll
            for (int p = 0; p < 2; ++p)
                ldsm4(bfr[p], base + TILEB + b_off + p * 16 * ROWB + ks * 32);
            #pragma unroll
            for (int f = 0; f < 2; ++f)
                #pragma unroll
                for (int j = 0; j < 4; ++j)
                    mma16816(acc[f][j], afr[f], &bfr[j >> 1][(j & 1) * 2]);
        }
    }

    // ---- epilogue: out = acc * 2^-28 ---------------------------------------
    #pragma unroll
    for (int f = 0; f < 2; ++f) {
        #pragma unroll
        for (int j = 0; j < 4; ++j) {
            const int nb = col0 + wn * 32 + j * 8 + (l & 3) * 2;
            #pragma unroll
            for (int h = 0; h < 2; ++h) {
                const int row = row0 + wm * 32 + f * 16 + h * 8 + (l >> 2);
                const float s = 1.0f / 268435456.0f;   // 2^-28
                *(float2*)(Cout + (size_t)row * DIM_ + nb) =
                    make_float2(acc[f][j][2 * h] * s, acc[f][j][2 * h + 1] * s);
            }
        }
    }
}

// ---------------- host ------------------------------------------------------
extern "C" void kernel_launch(void* const* d_in, const int* in_sizes, int n_in,
                              void* d_out, int out_size)
{
    const float* x  = (const float*)d_in[0];
    const float* Pi = (const float*)d_in[1];
    const float* cb = (const float*)d_in[2];
    float* out = (float*)d_out;

    unsigned short *x0, *x1, *p0, *p1, *th, *yh;
    cudaGetSymbolAddress((void**)&x0, g_x0);
    cudaGetSymbolAddress((void**)&x1, g_x1);
    cudaGetSymbolAddress((void**)&p0, g_p0);
    cudaGetSymbolAddress((void**)&p1, g_p1);
    cudaGetSymbolAddress((void**)&th, g_th);
    cudaGetSymbolAddress((void**)&yh, g_yh);

    const size_t N = (size_t)DIM_ * DIM_;
    const int smem1 = NSTG * STGB + 512 * 32 * 4;   // 163840 + 65536 = 229376
    const int smem2 = NSTG * STGB2;                 // 81920
    cudaFuncSetAttribute(gemm1_kernel,
                         cudaFuncAttributeMaxDynamicSharedMemorySize, smem1);
    cudaFuncSetAttribute(gemm2_kernel,
                         cudaFuncAttributeMaxDynamicSharedMemorySize, smem2);

    // 1) prep: 2^12 x -> (x0,x1) ; 2^16 Pi -> (p0,p1) ; fp16(2^16 Pi^T) -> th
    split2_kernel<4096><<<(int)(N / 4 / 256), 256>>>((const float4*)x,
                                                     (uint32_t*)x0, (uint32_t*)x1);
    split2_kernel<65536><<<(int)(N / 4 / 256), 256>>>((const float4*)Pi,
                                                      (uint32_t*)p0, (uint32_t*)p1);
    transhalf_kernel<<<dim3(DIM_ / 32, DIM_ / 32), dim3(32, 8)>>>(Pi, th);

    dim3 grid(DIM_ / BN, DIM_ / BM);
    // 2) GEMM1 (3-product, GRP=4 drain) + quantize -> yh = fp16(2^12 y~)
    gemm1_kernel<<<grid, 512, smem1>>>(x0, x1, p0, p1, cb, yh);
    // 3) GEMM2 (single product): out = (2^12 y~ @ 2^16 Pi) * 2^-28
    gemm2_kernel<<<grid, 512, smem2>>>(yh, th, out);
}

// round 12
// speedup vs baseline: 1.5527x; 1.0147x over previous
#include <cuda_runtime.h>
#include <cuda_fp16.h>
#include <cstdint>

#define DIM_ 4096
#define BM 128
#define BN 128
#define BKH 32               // fp16 k per chunk (64B per row)
#define NCH (DIM_ / BKH)     // 128 chunks
#define GRP 4                // chunks per RZ-chain group (drain period, GEMM1)
#define ROWB 80              // padded smem row stride (64B data + 16B pad), ldsm conflict-free
#define TILEB (BM * ROWB)    // 10240 B per tile
#define STGB (4 * TILEB)     // 4 tiles per stage (GEMM1: A0,A1,B0,B1)
#define NSTG 4
#define STGB2 (2 * TILEB)    // 2 tiles per stage (GEMM2: A,B)

// Scales (exact powers of 2): x*2^12 -> (x0,x1); Pi*2^16 -> (p0,p1);
// y~ stored fp16(c*2^12); Pi^T stored fp16(Pi^T*2^16).
// GEMM1 acc = 2^28*y, bnd*2^27. GEMM2 acc = 2^28*x~, out *2^-28.

// ---------------- scratch (allocation-free rule: __device__ globals) --------
__device__ unsigned short g_x0[(size_t)DIM_ * DIM_];
__device__ unsigned short g_x1[(size_t)DIM_ * DIM_];
__device__ unsigned short g_p0[(size_t)DIM_ * DIM_];
__device__ unsigned short g_p1[(size_t)DIM_ * DIM_];
__device__ unsigned short g_th[(size_t)DIM_ * DIM_];   // fp16(2^16 Pi^T), K-major
__device__ unsigned short g_yh[(size_t)DIM_ * DIM_];   // fp16(2^12 y~)

// ---------------- PTX helpers -----------------------------------------------
__device__ __forceinline__ uint32_t smem_u32(const void* p) {
    uint32_t a;
    asm("{ .reg .u64 t; cvta.to.shared.u64 t, %1; cvt.u32.u64 %0, t; }" : "=r"(a) : "l"(p));
    return a;
}
__device__ __forceinline__ void cpasync16(uint32_t sa, const void* g) {
    asm volatile("cp.async.cg.shared.global [%0], [%1], 16;" :: "r"(sa), "l"(g));
}
__device__ __forceinline__ void ldsm4(uint32_t* r, uint32_t a) {
    asm volatile("ldmatrix.sync.aligned.m8n8.x4.shared.b16 {%0,%1,%2,%3}, [%4];"
                 : "=r"(r[0]), "=r"(r[1]), "=r"(r[2]), "=r"(r[3]) : "r"(a));
}
__device__ __forceinline__ void mma16816(float* d, const uint32_t* a, const uint32_t* b) {
    asm volatile("mma.sync.aligned.m16n8k16.row.col.f32.f16.f16.f32 "
                 "{%0,%1,%2,%3}, {%4,%5,%6,%7}, {%8,%9}, {%0,%1,%2,%3};"
                 : "+f"(d[0]), "+f"(d[1]), "+f"(d[2]), "+f"(d[3])
                 : "r"(a[0]), "r"(a[1]), "r"(a[2]), "r"(a[3]), "r"(b[0]), "r"(b[1]));
}
#define CP_COMMIT() asm volatile("cp.async.commit_group;" ::: "memory")
#define CP_WAIT2()  asm volatile("cp.async.wait_group 2;" ::: "memory")

// ---------------- fp16 2-split (Markidis, pre-scaled) -----------------------
__device__ __forceinline__ void hsplit2(float v, unsigned short& b0, unsigned short& b1) {
    __half h0 = __float2half_rn(v);
    float r = v - __half2float(h0);
    __half h1 = __float2half_rn(r);
    b0 = *reinterpret_cast<unsigned short*>(&h0);
    b1 = *reinterpret_cast<unsigned short*>(&h1);
}

template<int SCALE>
__global__ void split2_kernel(const float4* __restrict__ in,
                              uint32_t* __restrict__ o0, uint32_t* __restrict__ o1) {
    int i = blockIdx.x * blockDim.x + threadIdx.x;
    float4 v = in[i];
    const float s = (float)SCALE;
    unsigned short a0[4], a1[4];
    hsplit2(v.x * s, a0[0], a1[0]);
    hsplit2(v.y * s, a0[1], a1[1]);
    hsplit2(v.z * s, a0[2], a1[2]);
    hsplit2(v.w * s, a0[3], a1[3]);
    o0[2 * i] = a0[0] | ((uint32_t)a0[1] << 16); o0[2 * i + 1] = a0[2] | ((uint32_t)a0[3] << 16);
    o1[2 * i] = a1[0] | ((uint32_t)a1[1] << 16); o1[2 * i + 1] = a1[2] | ((uint32_t)a1[3] << 16);
}

// Pi -> fp16(2^16 Pi^T), tiled transpose
__global__ void transhalf_kernel(const float* __restrict__ Pi,
                                 unsigned short* __restrict__ th) {
    __shared__ float tile[32][33];
    int tx = threadIdx.x, ty = threadIdx.y;
    int c0 = blockIdx.x * 32, r0 = blockIdx.y * 32;
    #pragma unroll
    for (int i = 0; i < 4; ++i)
        tile[ty + 8 * i][tx] = Pi[(size_t)(r0 + ty + 8 * i) * DIM_ + c0 + tx];
    __syncthreads();
    #pragma unroll
    for (int i = 0; i < 4; ++i) {
        __half h = __float2half_rn(tile[tx][ty + 8 * i] * 65536.0f);
        th[(size_t)(c0 + ty + 8 * i) * DIM_ + r0 + tx] = *reinterpret_cast<unsigned short*>(&h);
    }
}

// ---------------- GEMM1: 3-product split HMMA + quantize --------------------
// 256 threads, 8 warps in 2x4 grid, warp tile 64x32, register RZ-drain.
__global__ __launch_bounds__(256, 1)
void gemm1_kernel(const unsigned short* __restrict__ A0, const unsigned short* __restrict__ A1,
                  const unsigned short* __restrict__ Bm0, const unsigned short* __restrict__ Bm1,
                  const float* __restrict__ cb, unsigned short* __restrict__ Yh)
{
    extern __shared__ char smem[];
    const uint32_t sb = smem_u32(smem);
    __shared__ float s_bnd[15];        // 2^27 * (c_i + c_{i+1})
    __shared__ uint32_t s_cbh[16];     // fp16(2^12 * codebook), low 16 bits

    const int tid = threadIdx.x;
    const int w = tid >> 5, l = tid & 31;
    const int wm = w >> 2, wn = w & 3;          // 2x4 warp grid, warp tile 64x32
    const int row0 = blockIdx.y * BM;
    const int col0 = blockIdx.x * BN;

    if (tid < 16) {
        __half h = __float2half_rn(cb[tid] * 4096.0f);
        s_cbh[tid] = (uint32_t)(*reinterpret_cast<unsigned short*>(&h));
    }
    if (tid < 15) s_bnd[tid] = (cb[tid] + cb[tid + 1]) * 134217728.0f;  // 2^27

    const unsigned short* srcs[4] = {A0, A1, Bm0, Bm1};
    const int rb[4] = {row0, row0, col0, col0};

    // 512 x 16B chunks per tile; 256 threads -> 2 each
    const unsigned short* gp[4][2];
    uint32_t swr[2];
    #pragma unroll
    for (int i = 0; i < 2; ++i) {
        const int id = i * 256 + tid;
        const int r = id >> 2, c = id & 3;
        swr[i] = r * ROWB + c * 16;
        #pragma unroll
        for (int t = 0; t < 4; ++t)
            gp[t][i] = srcs[t] + (size_t)(rb[t] + r) * DIM_ + c * 8;
    }

    auto load_chunk = [&](int ch, int st) {
        const int k0 = ch * BKH;
        const uint32_t stg = sb + st * STGB;
        #pragma unroll
        for (int t = 0; t < 4; ++t)
            #pragma unroll
            for (int i = 0; i < 2; ++i)
                cpasync16(stg + t * TILEB + swr[i], gp[t][i] + k0);
        CP_COMMIT();
    };

    float acc[4][4][4];     // RZ-chained partials (reset every GRP chunks)
    float racc[4][4][4];    // RN register totals
    #pragma unroll
    for (int f = 0; f < 4; ++f)
        #pragma unroll
        for (int j = 0; j < 4; ++j)
            #pragma unroll
            for (int q = 0; q < 4; ++q) { acc[f][j][q] = 0.0f; racc[f][j][q] = 0.0f; }

    const uint32_t a_off = (uint32_t)(wm * 64 + (l & 15)) * ROWB + (l >> 4) * 16;
    const uint32_t b_off = (uint32_t)(wn * 32 + (l & 7) + ((l >> 4) & 1) * 8) * ROWB
                         + ((l >> 3) & 1) * 16;

    load_chunk(0, 0);
    load_chunk(1, 1);
    load_chunk(2, 2);

    for (int t = 0; t < NCH; ++t) {
        const int st = t & 3;
        CP_WAIT2();                      // uniform commits: chunk t arrived
        __syncthreads();
        if (t + 3 < NCH) load_chunk(t + 3, (t + 3) & 3);
        else             CP_COMMIT();    // empty group keeps pending-count exact

        const uint32_t base = sb + st * STGB;
        #pragma unroll
        for (int ks = 0; ks < 2; ++ks) {
            uint32_t afr[2][4][4];              // [split][mfrag 16-rows][4]
            #pragma unroll
            for (int s = 0; s < 2; ++s)
                #pragma unroll
                for (int f = 0; f < 4; ++f)
                    ldsm4(afr[s][f], base + s * TILEB + a_off + f * 16 * ROWB + ks * 32);

            #pragma unroll
            for (int sB = 0; sB < 2; ++sB) {
                uint32_t bfr[2][4];
                #pragma unroll
                for (int p = 0; p < 2; ++p)
                    ldsm4(bfr[p], base + (2 + sB) * TILEB + b_off + p * 16 * ROWB + ks * 32);
                // sB==0: a0*b0 + a1*b0 ; sB==1: a0*b1
                #pragma unroll
                for (int f = 0; f < 4; ++f)
                    #pragma unroll
                    for (int j = 0; j < 4; ++j)
                        mma16816(acc[f][j], afr[0][f], &bfr[j >> 1][(j & 1) * 2]);
                if (sB == 0) {
                    #pragma unroll
                    for (int f = 0; f < 4; ++f)
                        #pragma unroll
                        for (int j = 0; j < 4; ++j)
                            mma16816(acc[f][j], afr[1][f], &bfr[j >> 1][(j & 1) * 2]);
                }
            }
        }

        // group drain: RN-add partials into register totals, reset RZ chain
        if ((t & (GRP - 1)) == (GRP - 1)) {
            #pragma unroll
            for (int f = 0; f < 4; ++f)
                #pragma unroll
                for (int j = 0; j < 4; ++j)
                    #pragma unroll
                    for (int q = 0; q < 4; ++q) {
                        racc[f][j][q] += acc[f][j][q];
                        acc[f][j][q] = 0.0f;
                    }
        }
    }

    // ---- epilogue: quantize -> single fp16 y~ -------------------------------
    // m = wm*64 + f*16 + h*8 + l/4 ; n = wn*32 + j*8 + 2*(l&3) + (q&1)
    #pragma unroll
    for (int f = 0; f < 4; ++f) {
        #pragma unroll
        for (int j = 0; j < 4; ++j) {
            const int nb = col0 + wn * 32 + j * 8 + (l & 3) * 2;
            #pragma unroll
            for (int h = 0; h < 2; ++h) {
                const int row = row0 + wm * 64 + f * 16 + h * 8 + (l >> 2);
                const float va = racc[f][j][2 * h];
                const float vb = racc[f][j][2 * h + 1];
                int ia = 0, ib = 0;
                #pragma unroll
                for (int q = 0; q < 15; ++q) {
                    ia += (va > s_bnd[q]) ? 1 : 0;
                    ib += (vb > s_bnd[q]) ? 1 : 0;
                }
                const size_t o = ((size_t)row * DIM_ + nb) >> 1;
                ((uint32_t*)Yh)[o] = s_cbh[ia] | (s_cbh[ib] << 16);
            }
        }
    }
}

// ---------------- GEMM2: plain single-product fp16 HMMA (unchanged R10) -----
__global__ __launch_bounds__(512, 1)
void gemm2_kernel(const unsigned short* __restrict__ A, const unsigned short* __restrict__ B,
                  float* __restrict__ Cout)
{
    extern __shared__ char smem[];
    const uint32_t sb = smem_u32(smem);

    const int tid = threadIdx.x;
    const int w = tid >> 5, l = tid & 31;
    const int wm = w & 3, wn = w >> 2;          // 4x4 warp grid, warp tile 32x32
    const int row0 = blockIdx.y * BM;
    const int col0 = blockIdx.x * BN;

    const int cr = tid >> 2, cc = tid & 3;
    const unsigned short* gpa = A + (size_t)(row0 + cr) * DIM_ + cc * 8;
    const unsigned short* gpb = B + (size_t)(col0 + cr) * DIM_ + cc * 8;
    const uint32_t swr = cr * ROWB + cc * 16;

    auto load_chunk = [&](int ch, int st) {
        const int k0 = ch * BKH;
        const uint32_t stg = sb + st * STGB2;
        cpasync16(stg + swr, gpa + k0);
        cpasync16(stg + TILEB + swr, gpb + k0);
        CP_COMMIT();
    };

    float acc[2][4][4];
    #pragma unroll
    for (int f = 0; f < 2; ++f)
        #pragma unroll
        for (int j = 0; j < 4; ++j)
            #pragma unroll
            for (int q = 0; q < 4; ++q) acc[f][j][q] = 0.0f;

    const uint32_t a_off = (uint32_t)(wm * 32 + (l & 15)) * ROWB + (l >> 4) * 16;
    const uint32_t b_off = (uint32_t)(wn * 32 + (l & 7) + ((l >> 4) & 1) * 8) * ROWB
                         + ((l >> 3) & 1) * 16;

    load_chunk(0, 0);
    load_chunk(1, 1);
    load_chunk(2, 2);

    for (int t = 0; t < NCH; ++t) {
        const int st = t & 3;
        CP_WAIT2();
        __syncthreads();
        if (t + 3 < NCH) load_chunk(t + 3, (t + 3) & 3);
        else             CP_COMMIT();

        const uint32_t base = sb + st * STGB2;
        #pragma unroll
        for (int ks = 0; ks < 2; ++ks) {
            uint32_t afr[2][4];
            #pragma unroll
            for (int f = 0; f < 2; ++f)
                ldsm4(afr[f], base + a_off + f * 16 * ROWB + ks * 32);
            uint32_t bfr[2][4];
            #pragma unroll
            for (int p = 0; p < 2; ++p)
                ldsm4(bfr[p], base + TILEB + b_off + p * 16 * ROWB + ks * 32);
            #pragma unroll
            for (int f = 0; f < 2; ++f)
                #pragma unroll
                for (int j = 0; j < 4; ++j)
                    mma16816(acc[f][j], afr[f], &bfr[j >> 1][(j & 1) * 2]);
        }
    }

    #pragma unroll
    for (int f = 0; f < 2; ++f) {
        #pragma unroll
        for (int j = 0; j < 4; ++j) {
            const int nb = col0 + wn * 32 + j * 8 + (l & 3) * 2;
            #pragma unroll
            for (int h = 0; h < 2; ++h) {
                const int row = row0 + wm * 32 + f * 16 + h * 8 + (l >> 2);
                const float s = 1.0f / 268435456.0f;   // 2^-28
                *(float2*)(Cout + (size_t)row * DIM_ + nb) =
                    make_float2(acc[f][j][2 * h] * s, acc[f][j][2 * h + 1] * s);
            }
        }
    }
}

// ---------------- host ------------------------------------------------------
extern "C" void kernel_launch(void* const* d_in, const int* in_sizes, int n_in,
                              void* d_out, int out_size)
{
    const float* x  = (const float*)d_in[0];
    const float* Pi = (const float*)d_in[1];
    const float* cb = (const float*)d_in[2];
    float* out = (float*)d_out;

    unsigned short *x0, *x1, *p0, *p1, *th, *yh;
    cudaGetSymbolAddress((void**)&x0, g_x0);
    cudaGetSymbolAddress((void**)&x1, g_x1);
    cudaGetSymbolAddress((void**)&p0, g_p0);
    cudaGetSymbolAddress((void**)&p1, g_p1);
    cudaGetSymbolAddress((void**)&th, g_th);
    cudaGetSymbolAddress((void**)&yh, g_yh);

    const size_t N = (size_t)DIM_ * DIM_;
    const int smem1 = NSTG * STGB;    // 163840 (drain now in registers)
    const int smem2 = NSTG * STGB2;   // 81920
    cudaFuncSetAttribute(gemm1_kernel,
                         cudaFuncAttributeMaxDynamicSharedMemorySize, smem1);
    cudaFuncSetAttribute(gemm2_kernel,
                         cudaFuncAttributeMaxDynamicSharedMemorySize, smem2);

    // 1) prep: 2^12 x -> (x0,x1) ; 2^16 Pi -> (p0,p1) ; fp16(2^16 Pi^T) -> th
    split2_kernel<4096><<<(int)(N / 4 / 256), 256>>>((const float4*)x,
                                                     (uint32_t*)x0, (uint32_t*)x1);
    split2_kernel<65536><<<(int)(N / 4 / 256), 256>>>((const float4*)Pi,
                                                      (uint32_t*)p0, (uint32_t*)p1);
    transhalf_kernel<<<dim3(DIM_ / 32, DIM_ / 32), dim3(32, 8)>>>(Pi, th);

    dim3 grid(DIM_ / BN, DIM_ / BM);
    // 2) GEMM1 (3-product, GRP=4 register drain) + quantize -> yh
    gemm1_kernel<<<grid, 256, smem1>>>(x0, x1, p0, p1, cb, yh);
    // 3) GEMM2 (single product): out = (2^12 y~ @ 2^16 Pi) * 2^-28
    gemm2_kernel<<<grid, 512, smem2>>>(yh, th, out);
}

// round 13
// speedup vs baseline: 1.8879x; 1.2159x over previous
#include <cuda_runtime.h>
#include <cuda_fp16.h>
#include <cstdint>

#define DIM_ 4096
#define BM 128
#define BN 128

// ---- GEMM1 geometry: BKH1=64, 128B rows, XOR-swizzled SW128 ----------------
#define BKH1 64
#define NCH1 (DIM_ / BKH1)    // 64 chunks
#define GRP1 2                // drain every 2 chunks = 128 k (same RZ chain as R11)
#define TILE1B (BM * 128)     // 16384 B per tile
#define STG1B (4 * TILE1B)    // 65536 B per stage (A0,A1,B0,B1)
#define NSTG1 3               // 196608 B total

// ---- GEMM2 geometry: unchanged R10/R11 (pad-80 rows, BKH=32) ---------------
#define BKH 32
#define NCH (DIM_ / BKH)
#define ROWB 80
#define TILEB (BM * ROWB)
#define STGB2 (2 * TILEB)
#define NSTG 4

// Scales (exact powers of 2): x*2^12 -> (x0,x1); Pi*2^16 -> (p0,p1);
// y~ stored fp16(c*2^12); Pi^T stored fp16(Pi^T*2^16).
// GEMM1 acc = 2^28*y, bnd*2^27. GEMM2 acc = 2^28*x~, out *2^-28.

// ---------------- scratch (allocation-free rule: __device__ globals) --------
__device__ unsigned short g_x0[(size_t)DIM_ * DIM_];
__device__ unsigned short g_x1[(size_t)DIM_ * DIM_];
__device__ unsigned short g_p0[(size_t)DIM_ * DIM_];
__device__ unsigned short g_p1[(size_t)DIM_ * DIM_];
__device__ unsigned short g_th[(size_t)DIM_ * DIM_];   // fp16(2^16 Pi^T), K-major
__device__ unsigned short g_yh[(size_t)DIM_ * DIM_];   // fp16(2^12 y~)

// ---------------- PTX helpers -----------------------------------------------
__device__ __forceinline__ uint32_t smem_u32(const void* p) {
    uint32_t a;
    asm("{ .reg .u64 t; cvta.to.shared.u64 t, %1; cvt.u32.u64 %0, t; }" : "=r"(a) : "l"(p));
    return a;
}
__device__ __forceinline__ void cpasync16(uint32_t sa, const void* g) {
    asm volatile("cp.async.cg.shared.global [%0], [%1], 16;" :: "r"(sa), "l"(g));
}
__device__ __forceinline__ void ldsm4(uint32_t* r, uint32_t a) {
    asm volatile("ldmatrix.sync.aligned.m8n8.x4.shared.b16 {%0,%1,%2,%3}, [%4];"
                 : "=r"(r[0]), "=r"(r[1]), "=r"(r[2]), "=r"(r[3]) : "r"(a));
}
__device__ __forceinline__ void mma16816(float* d, const uint32_t* a, const uint32_t* b) {
    asm volatile("mma.sync.aligned.m16n8k16.row.col.f32.f16.f16.f32 "
                 "{%0,%1,%2,%3}, {%4,%5,%6,%7}, {%8,%9}, {%0,%1,%2,%3};"
                 : "+f"(d[0]), "+f"(d[1]), "+f"(d[2]), "+f"(d[3])
                 : "r"(a[0]), "r"(a[1]), "r"(a[2]), "r"(a[3]), "r"(b[0]), "r"(b[1]));
}
#define CP_COMMIT() asm volatile("cp.async.commit_group;" ::: "memory")
#define CP_WAIT1()  asm volatile("cp.async.wait_group 1;" ::: "memory")
#define CP_WAIT2()  asm volatile("cp.async.wait_group 2;" ::: "memory")

// ---------------- fp16 2-split (Markidis, pre-scaled) -----------------------
__device__ __forceinline__ void hsplit2(float v, unsigned short& b0, unsigned short& b1) {
    __half h0 = __float2half_rn(v);
    float r = v - __half2float(h0);
    __half h1 = __float2half_rn(r);
    b0 = *reinterpret_cast<unsigned short*>(&h0);
    b1 = *reinterpret_cast<unsigned short*>(&h1);
}

template<int SCALE>
__global__ void split2_kernel(const float4* __restrict__ in,
                              uint32_t* __restrict__ o0, uint32_t* __restrict__ o1) {
    int i = blockIdx.x * blockDim.x + threadIdx.x;
    float4 v = in[i];
    const float s = (float)SCALE;
    unsigned short a0[4], a1[4];
    hsplit2(v.x * s, a0[0], a1[0]);
    hsplit2(v.y * s, a0[1], a1[1]);
    hsplit2(v.z * s, a0[2], a1[2]);
    hsplit2(v.w * s, a0[3], a1[3]);
    o0[2 * i] = a0[0] | ((uint32_t)a0[1] << 16); o0[2 * i + 1] = a0[2] | ((uint32_t)a0[3] << 16);
    o1[2 * i] = a1[0] | ((uint32_t)a1[1] << 16); o1[2 * i + 1] = a1[2] | ((uint32_t)a1[3] << 16);
}

// Pi -> fp16(2^16 Pi^T), tiled transpose
__global__ void transhalf_kernel(const float* __restrict__ Pi,
                                 unsigned short* __restrict__ th) {
    __shared__ float tile[32][33];
    int tx = threadIdx.x, ty = threadIdx.y;
    int c0 = blockIdx.x * 32, r0 = blockIdx.y * 32;
    #pragma unroll
    for (int i = 0; i < 4; ++i)
        tile[ty + 8 * i][tx] = Pi[(size_t)(r0 + ty + 8 * i) * DIM_ + c0 + tx];
    __syncthreads();
    #pragma unroll
    for (int i = 0; i < 4; ++i) {
        __half h = __float2half_rn(tile[tx][ty + 8 * i] * 65536.0f);
        th[(size_t)(c0 + ty + 8 * i) * DIM_ + r0 + tx] = *reinterpret_cast<unsigned short*>(&h);
    }
}

// ---------------- GEMM1: 3-product split HMMA + quantize --------------------
// 256 threads, 2x4 warp grid (64x32 warp tiles), BKH1=64 chunks, XOR swizzle,
// NSTG1=3 pipeline, register RZ-drain every GRP1 chunks.
__global__ __launch_bounds__(256, 1)
void gemm1_kernel(const unsigned short* __restrict__ A0, const unsigned short* __restrict__ A1,
                  const unsigned short* __restrict__ Bm0, const unsigned short* __restrict__ Bm1,
                  const float* __restrict__ cb, unsigned short* __restrict__ Yh)
{
    extern __shared__ char smem[];
    const uint32_t sb = smem_u32(smem);
    __shared__ float s_bnd[15];        // 2^27 * (c_i + c_{i+1})
    __shared__ uint32_t s_cbh[16];     // fp16(2^12 * codebook), low 16 bits

    const int tid = threadIdx.x;
    const int w = tid >> 5, l = tid & 31;
    const int wm = w >> 2, wn = w & 3;          // 2x4 warp grid, warp tile 64x32
    const int row0 = blockIdx.y * BM;
    const int col0 = blockIdx.x * BN;

    if (tid < 16) {
        __half h = __float2half_rn(cb[tid] * 4096.0f);
        s_cbh[tid] = (uint32_t)(*reinterpret_cast<unsigned short*>(&h));
    }
    if (tid < 15) s_bnd[tid] = (cb[tid] + cb[tid + 1]) * 134217728.0f;  // 2^27

    const unsigned short* srcs[4] = {A0, A1, Bm0, Bm1};
    const int rb[4] = {row0, row0, col0, col0};

    // cp.async: 1024 x 16B per tile; 256 threads -> 4 each (i = 0..3)
    // id = i*256 + tid ; r = id>>3 (0..127), c = id&7 ; swizzled col = c ^ (r&7)
    const unsigned short* tbase[4];
    #pragma unroll
    for (int t = 0; t < 4; ++t) tbase[t] = srcs[t] + (size_t)rb[t] * DIM_;
    uint32_t goff[4], soff[4];
    #pragma unroll
    for (int i = 0; i < 4; ++i) {
        const int id = i * 256 + tid;
        const int r = id >> 3, c = id & 7;
        goff[i] = (uint32_t)(r * DIM_ + c * 8);
        soff[i] = (uint32_t)(r * 128 + ((c ^ (r & 7)) * 16));
    }

    auto load_chunk = [&](int ch, int st) {
        const int k0 = ch * BKH1;
        const uint32_t stg = sb + st * STG1B;
        #pragma unroll
        for (int t = 0; t < 4; ++t)
            #pragma unroll
            for (int i = 0; i < 4; ++i)
                cpasync16(stg + t * TILE1B + soff[i], tbase[t] + goff[i] + k0);
        CP_COMMIT();
    };

    float acc[4][4][4];     // RZ-chained partials (reset every GRP1 chunks)
    float racc[4][4][4];    // RN register totals
    #pragma unroll
    for (int f = 0; f < 4; ++f)
        #pragma unroll
        for (int j = 0; j < 4; ++j)
            #pragma unroll
            for (int q = 0; q < 4; ++q) { acc[f][j][q] = 0.0f; racc[f][j][q] = 0.0f; }

    // ldsm lane-constant pieces (swizzle xor = l&7 for all our rows)
    const int lxor = l & 7;
    const int a_row = wm * 64 + (l & 15);                     // + f*16
    const int a_c0  = l >> 4;                                 // + 2*ks
    const int b_row = wn * 32 + (l & 7) + ((l >> 4) & 1) * 8; // + p*16
    const int b_c0  = (l >> 3) & 1;                           // + 2*ks

    load_chunk(0, 0);
    load_chunk(1, 1);

    for (int t = 0; t < NCH1; ++t) {
        const int st = t % 3;
        CP_WAIT1();                      // uniform commits: chunk t arrived
        __syncthreads();
        if (t + 2 < NCH1) load_chunk(t + 2, (t + 2) % 3);
        else              CP_COMMIT();   // empty group keeps pending-count exact

        const uint32_t base = sb + st * STG1B;
        #pragma unroll
        for (int ks = 0; ks < 4; ++ks) {
            uint32_t afr[2][4][4];              // [split][mfrag 16-rows][4]
            #pragma unroll
            for (int s = 0; s < 2; ++s)
                #pragma unroll
                for (int f = 0; f < 4; ++f)
                    ldsm4(afr[s][f], base + s * TILE1B
                          + (a_row + f * 16) * 128 + (((a_c0 + 2 * ks) ^ lxor) * 16));

            #pragma unroll
            for (int sB = 0; sB < 2; ++sB) {
                uint32_t bfr[2][4];
                #pragma unroll
                for (int p = 0; p < 2; ++p)
                    ldsm4(bfr[p], base + (2 + sB) * TILE1B
                          + (b_row + p * 16) * 128 + (((b_c0 + 2 * ks) ^ lxor) * 16));
                // sB==0: a0*b0 + a1*b0 ; sB==1: a0*b1
                #pragma unroll
                for (int f = 0; f < 4; ++f)
                    #pragma unroll
                    for (int j = 0; j < 4; ++j)
                        mma16816(acc[f][j], afr[0][f], &bfr[j >> 1][(j & 1) * 2]);
                if (sB == 0) {
                    #pragma unroll
                    for (int f = 0; f < 4; ++f)
                        #pragma unroll
                        for (int j = 0; j < 4; ++j)
                            mma16816(acc[f][j], afr[1][f], &bfr[j >> 1][(j & 1) * 2]);
                }
            }
        }

        // group drain: RN-add partials into register totals, reset RZ chain
        if ((t & (GRP1 - 1)) == (GRP1 - 1)) {
            #pragma unroll
            for (int f = 0; f < 4; ++f)
                #pragma unroll
                for (int j = 0; j < 4; ++j)
                    #pragma unroll
                    for (int q = 0; q < 4; ++q) {
                        racc[f][j][q] += acc[f][j][q];
                        acc[f][j][q] = 0.0f;
                    }
        }
    }

    // ---- epilogue: quantize -> single fp16 y~ -------------------------------
    // m = wm*64 + f*16 + h*8 + l/4 ; n = wn*32 + j*8 + 2*(l&3) + (q&1)
    #pragma unroll
    for (int f = 0; f < 4; ++f) {
        #pragma unroll
        for (int j = 0; j < 4; ++j) {
            const int nb = col0 + wn * 32 + j * 8 + (l & 3) * 2;
            #pragma unroll
            for (int h = 0; h < 2; ++h) {
                const int row = row0 + wm * 64 + f * 16 + h * 8 + (l >> 2);
                const float va = racc[f][j][2 * h];
                const float vb = racc[f][j][2 * h + 1];
                int ia = 0, ib = 0;
                #pragma unroll
                for (int q = 0; q < 15; ++q) {
                    ia += (va > s_bnd[q]) ? 1 : 0;
                    ib += (vb > s_bnd[q]) ? 1 : 0;
                }
                const size_t o = ((size_t)row * DIM_ + nb) >> 1;
                ((uint32_t*)Yh)[o] = s_cbh[ia] | (s_cbh[ib] << 16);
            }
        }
    }
}

// ---------------- GEMM2: plain single-product fp16 HMMA (unchanged R10) -----
__global__ __launch_bounds__(512, 1)
void gemm2_kernel(const unsigned short* __restrict__ A, const unsigned short* __restrict__ B,
                  float* __restrict__ Cout)
{
    extern __shared__ char smem[];
    const uint32_t sb = smem_u32(smem);

    const int tid = threadIdx.x;
    const int w = tid >> 5, l = tid & 31;
    const int wm = w & 3, wn = w >> 2;          // 4x4 warp grid, warp tile 32x32
    const int row0 = blockIdx.y * BM;
    const int col0 = blockIdx.x * BN;

    const int cr = tid >> 2, cc = tid & 3;
    const unsigned short* gpa = A + (size_t)(row0 + cr) * DIM_ + cc * 8;
    const unsigned short* gpb = B + (size_t)(col0 + cr) * DIM_ + cc * 8;
    const uint32_t swr = cr * ROWB + cc * 16;

    auto load_chunk = [&](int ch, int st) {
        const int k0 = ch * BKH;
        const uint32_t stg = sb + st * STGB2;
        cpasync16(stg + swr, gpa + k0);
        cpasync16(stg + TILEB + swr, gpb + k0);
        CP_COMMIT();
    };

    float acc[2][4][4];
    #pragma unroll
    for (int f = 0; f < 2; ++f)
        #pragma unroll
        for (int j = 0; j < 4; ++j)
            #pragma unroll
            for (int q = 0; q < 4; ++q) acc[f][j][q] = 0.0f;

    const uint32_t a_off = (uint32_t)(wm * 32 + (l & 15)) * ROWB + (l >> 4) * 16;
    const uint32_t b_off = (uint32_t)(wn * 32 + (l & 7) + ((l >> 4) & 1) * 8) * ROWB
                         + ((l >> 3) & 1) * 16;

    load_chunk(0, 0);
    load_chunk(1, 1);
    load_chunk(2, 2);

    for (int t = 0; t < NCH; ++t) {
        const int st = t & 3;
        CP_WAIT2();
        __syncthreads();
        if (t + 3 < NCH) load_chunk(t + 3, (t + 3) & 3);
        else             CP_COMMIT();

        const uint32_t base = sb + st * STGB2;
        #pragma unroll
        for (int ks = 0; ks < 2; ++ks) {
            uint32_t afr[2][4];
            #pragma unroll
            for (int f = 0; f < 2; ++f)
                ldsm4(afr[f], base + a_off + f * 16 * ROWB + ks * 32);
            uint32_t bfr[2][4];
            #pragma unroll
            for (int p = 0; p < 2; ++p)
                ldsm4(bfr[p], base + TILEB + b_off + p * 16 * ROWB + ks * 32);
            #pragma unroll
            for (int f = 0; f < 2; ++f)
                #pragma unroll
                for (int j = 0; j < 4; ++j)
                    mma16816(acc[f][j], afr[f], &bfr[j >> 1][(j & 1) * 2]);
        }
    }

    #pragma unroll
    for (int f = 0; f < 2; ++f) {
        #pragma unroll
        for (int j = 0; j < 4; ++j) {
            const int nb = col0 + wn * 32 + j * 8 + (l & 3) * 2;
            #pragma unroll
            for (int h = 0; h < 2; ++h) {
                const int row = row0 + wm * 32 + f * 16 + h * 8 + (l >> 2);
                const float s = 1.0f / 268435456.0f;   // 2^-28
                *(float2*)(Cout + (size_t)row * DIM_ + nb) =
                    make_float2(acc[f][j][2 * h] * s, acc[f][j][2 * h + 1] * s);
            }
        }
    }
}

// ---------------- host ------------------------------------------------------
extern "C" void kernel_launch(void* const* d_in, const int* in_sizes, int n_in,
                              void* d_out, int out_size)
{
    const float* x  = (const float*)d_in[0];
    const float* Pi = (const float*)d_in[1];
    const float* cb = (const float*)d_in[2];
    float* out = (float*)d_out;

    unsigned short *x0, *x1, *p0, *p1, *th, *yh;
    cudaGetSymbolAddress((void**)&x0, g_x0);
    cudaGetSymbolAddress((void**)&x1, g_x1);
    cudaGetSymbolAddress((void**)&p0, g_p0);
    cudaGetSymbolAddress((void**)&p1, g_p1);
    cudaGetSymbolAddress((void**)&th, g_th);
    cudaGetSymbolAddress((void**)&yh, g_yh);

    const size_t N = (size_t)DIM_ * DIM_;
    const int smem1 = NSTG1 * STG1B;  // 196608
    const int smem2 = NSTG * STGB2;   // 81920
    cudaFuncSetAttribute(gemm1_kernel,
                         cudaFuncAttributeMaxDynamicSharedMemorySize, smem1);
    cudaFuncSetAttribute(gemm2_kernel,
                         cudaFuncAttributeMaxDynamicSharedMemorySize, smem2);

    // 1) prep: 2^12 x -> (x0,x1) ; 2^16 Pi -> (p0,p1) ; fp16(2^16 Pi^T) -> th
    split2_kernel<4096><<<(int)(N / 4 / 256), 256>>>((const float4*)x,
                                                     (uint32_t*)x0, (uint32_t*)x1);
    split2_kernel<65536><<<(int)(N / 4 / 256), 256>>>((const float4*)Pi,
                                                      (uint32_t*)p0, (uint32_t*)p1);
    transhalf_kernel<<<dim3(DIM_ / 32, DIM_ / 32), dim3(32, 8)>>>(Pi, th);

    dim3 grid(DIM_ / BN, DIM_ / BM);
    // 2) GEMM1 (3-product, BKH1=64, GRP1=2 register drain) + quantize -> yh
    gemm1_kernel<<<grid, 256, smem1>>>(x0, x1, p0, p1, cb, yh);
    // 3) GEMM2 (single product): out = (2^12 y~ @ 2^16 Pi) * 2^-28
    gemm2_kernel<<<grid, 512, smem2>>>(yh, th, out);
}

// round 14
// speedup vs baseline: 2.0124x; 1.0659x over previous
#include <cuda_runtime.h>
#include <cuda_fp16.h>
#include <cstdint>

#define DIM_ 4096
#define BM 128
#define BN 128

// ---- shared geometry: BKH=64, 128B rows, XOR-swizzled SW128 ----------------
#define BKH1 64
#define NCH1 (DIM_ / BKH1)    // 64 chunks
#define GRP1 2                // GEMM1: drain every 2 chunks = 128 k
#define TILE1B (BM * 128)     // 16384 B per tile
#define STG1B (4 * TILE1B)    // GEMM1 stage: 4 tiles (A0,A1,B0,B1)
#define NSTG1 3
#define STG2B (2 * TILE1B)    // GEMM2 stage: 2 tiles (A,B)

// Scales (exact powers of 2): x*2^12 -> (x0,x1); Pi*2^16 -> (p0,p1);
// y~ stored fp16(c*2^12); Pi^T stored fp16(Pi^T*2^16).
// GEMM1 acc = 2^28*y, bnd*2^27. GEMM2 acc = 2^28*x~, out *2^-28.

// ---------------- scratch (allocation-free rule: __device__ globals) --------
__device__ unsigned short g_x0[(size_t)DIM_ * DIM_];
__device__ unsigned short g_x1[(size_t)DIM_ * DIM_];
__device__ unsigned short g_p0[(size_t)DIM_ * DIM_];
__device__ unsigned short g_p1[(size_t)DIM_ * DIM_];
__device__ unsigned short g_th[(size_t)DIM_ * DIM_];   // fp16(2^16 Pi^T), K-major
__device__ unsigned short g_yh[(size_t)DIM_ * DIM_];   // fp16(2^12 y~)

// ---------------- PTX helpers -----------------------------------------------
__device__ __forceinline__ uint32_t smem_u32(const void* p) {
    uint32_t a;
    asm("{ .reg .u64 t; cvta.to.shared.u64 t, %1; cvt.u32.u64 %0, t; }" : "=r"(a) : "l"(p));
    return a;
}
__device__ __forceinline__ void cpasync16(uint32_t sa, const void* g) {
    asm volatile("cp.async.cg.shared.global [%0], [%1], 16;" :: "r"(sa), "l"(g));
}
__device__ __forceinline__ void ldsm4(uint32_t* r, uint32_t a) {
    asm volatile("ldmatrix.sync.aligned.m8n8.x4.shared.b16 {%0,%1,%2,%3}, [%4];"
                 : "=r"(r[0]), "=r"(r[1]), "=r"(r[2]), "=r"(r[3]) : "r"(a));
}
__device__ __forceinline__ void mma16816(float* d, const uint32_t* a, const uint32_t* b) {
    asm volatile("mma.sync.aligned.m16n8k16.row.col.f32.f16.f16.f32 "
                 "{%0,%1,%2,%3}, {%4,%5,%6,%7}, {%8,%9}, {%0,%1,%2,%3};"
                 : "+f"(d[0]), "+f"(d[1]), "+f"(d[2]), "+f"(d[3])
                 : "r"(a[0]), "r"(a[1]), "r"(a[2]), "r"(a[3]), "r"(b[0]), "r"(b[1]));
}
#define CP_COMMIT() asm volatile("cp.async.commit_group;" ::: "memory")
#define CP_WAIT1()  asm volatile("cp.async.wait_group 1;" ::: "memory")

// ---------------- fp16 2-split (Markidis, pre-scaled) -----------------------
__device__ __forceinline__ void hsplit2(float v, unsigned short& b0, unsigned short& b1) {
    __half h0 = __float2half_rn(v);
    float r = v - __half2float(h0);
    __half h1 = __float2half_rn(r);
    b0 = *reinterpret_cast<unsigned short*>(&h0);
    b1 = *reinterpret_cast<unsigned short*>(&h1);
}

template<int SCALE>
__global__ void split2_kernel(const float4* __restrict__ in,
                              uint32_t* __restrict__ o0, uint32_t* __restrict__ o1) {
    int i = blockIdx.x * blockDim.x + threadIdx.x;
    float4 v = in[i];
    const float s = (float)SCALE;
    unsigned short a0[4], a1[4];
    hsplit2(v.x * s, a0[0], a1[0]);
    hsplit2(v.y * s, a0[1], a1[1]);
    hsplit2(v.z * s, a0[2], a1[2]);
    hsplit2(v.w * s, a0[3], a1[3]);
    o0[2 * i] = a0[0] | ((uint32_t)a0[1] << 16); o0[2 * i + 1] = a0[2] | ((uint32_t)a0[3] << 16);
    o1[2 * i] = a1[0] | ((uint32_t)a1[1] << 16); o1[2 * i + 1] = a1[2] | ((uint32_t)a1[3] << 16);
}

// Pi -> fp16(2^16 Pi^T), tiled transpose
__global__ void transhalf_kernel(const float* __restrict__ Pi,
                                 unsigned short* __restrict__ th) {
    __shared__ float tile[32][33];
    int tx = threadIdx.x, ty = threadIdx.y;
    int c0 = blockIdx.x * 32, r0 = blockIdx.y * 32;
    #pragma unroll
    for (int i = 0; i < 4; ++i)
        tile[ty + 8 * i][tx] = Pi[(size_t)(r0 + ty + 8 * i) * DIM_ + c0 + tx];
    __syncthreads();
    #pragma unroll
    for (int i = 0; i < 4; ++i) {
        __half h = __float2half_rn(tile[tx][ty + 8 * i] * 65536.0f);
        th[(size_t)(c0 + ty + 8 * i) * DIM_ + r0 + tx] = *reinterpret_cast<unsigned short*>(&h);
    }
}

// ---------------- GEMM1: 3-product split HMMA + quantize (unchanged R12) ----
__global__ __launch_bounds__(256, 1)
void gemm1_kernel(const unsigned short* __restrict__ A0, const unsigned short* __restrict__ A1,
                  const unsigned short* __restrict__ Bm0, const unsigned short* __restrict__ Bm1,
                  const float* __restrict__ cb, unsigned short* __restrict__ Yh)
{
    extern __shared__ char smem[];
    const uint32_t sb = smem_u32(smem);
    __shared__ float s_bnd[15];        // 2^27 * (c_i + c_{i+1})
    __shared__ uint32_t s_cbh[16];     // fp16(2^12 * codebook), low 16 bits

    const int tid = threadIdx.x;
    const int w = tid >> 5, l = tid & 31;
    const int wm = w >> 2, wn = w & 3;          // 2x4 warp grid, warp tile 64x32
    const int row0 = blockIdx.y * BM;
    const int col0 = blockIdx.x * BN;

    if (tid < 16) {
        __half h = __float2half_rn(cb[tid] * 4096.0f);
        s_cbh[tid] = (uint32_t)(*reinterpret_cast<unsigned short*>(&h));
    }
    if (tid < 15) s_bnd[tid] = (cb[tid] + cb[tid + 1]) * 134217728.0f;  // 2^27

    const unsigned short* srcs[4] = {A0, A1, Bm0, Bm1};
    const int rb[4] = {row0, row0, col0, col0};

    const unsigned short* tbase[4];
    #pragma unroll
    for (int t = 0; t < 4; ++t) tbase[t] = srcs[t] + (size_t)rb[t] * DIM_;
    uint32_t goff[4], soff[4];
    #pragma unroll
    for (int i = 0; i < 4; ++i) {
        const int id = i * 256 + tid;
        const int r = id >> 3, c = id & 7;
        goff[i] = (uint32_t)(r * DIM_ + c * 8);
        soff[i] = (uint32_t)(r * 128 + ((c ^ (r & 7)) * 16));
    }

    auto load_chunk = [&](int ch, int st) {
        const int k0 = ch * BKH1;
        const uint32_t stg = sb + st * STG1B;
        #pragma unroll
        for (int t = 0; t < 4; ++t)
            #pragma unroll
            for (int i = 0; i < 4; ++i)
                cpasync16(stg + t * TILE1B + soff[i], tbase[t] + goff[i] + k0);
        CP_COMMIT();
    };

    float acc[4][4][4];     // RZ-chained partials (reset every GRP1 chunks)
    float racc[4][4][4];    // RN register totals
    #pragma unroll
    for (int f = 0; f < 4; ++f)
        #pragma unroll
        for (int j = 0; j < 4; ++j)
            #pragma unroll
            for (int q = 0; q < 4; ++q) { acc[f][j][q] = 0.0f; racc[f][j][q] = 0.0f; }

    const int lxor = l & 7;
    const int a_row = wm * 64 + (l & 15);
    const int a_c0  = l >> 4;
    const int b_row = wn * 32 + (l & 7) + ((l >> 4) & 1) * 8;
    const int b_c0  = (l >> 3) & 1;

    load_chunk(0, 0);
    load_chunk(1, 1);

    for (int t = 0; t < NCH1; ++t) {
        const int st = t % 3;
        CP_WAIT1();
        __syncthreads();
        if (t + 2 < NCH1) load_chunk(t + 2, (t + 2) % 3);
        else              CP_COMMIT();

        const uint32_t base = sb + st * STG1B;
        #pragma unroll
        for (int ks = 0; ks < 4; ++ks) {
            uint32_t afr[2][4][4];
            #pragma unroll
            for (int s = 0; s < 2; ++s)
                #pragma unroll
                for (int f = 0; f < 4; ++f)
                    ldsm4(afr[s][f], base + s * TILE1B
                          + (a_row + f * 16) * 128 + (((a_c0 + 2 * ks) ^ lxor) * 16));

            #pragma unroll
            for (int sB = 0; sB < 2; ++sB) {
                uint32_t bfr[2][4];
                #pragma unroll
                for (int p = 0; p < 2; ++p)
                    ldsm4(bfr[p], base + (2 + sB) * TILE1B
                          + (b_row + p * 16) * 128 + (((b_c0 + 2 * ks) ^ lxor) * 16));
                #pragma unroll
                for (int f = 0; f < 4; ++f)
                    #pragma unroll
                    for (int j = 0; j < 4; ++j)
                        mma16816(acc[f][j], afr[0][f], &bfr[j >> 1][(j & 1) * 2]);
                if (sB == 0) {
                    #pragma unroll
                    for (int f = 0; f < 4; ++f)
                        #pragma unroll
                        for (int j = 0; j < 4; ++j)
                            mma16816(acc[f][j], afr[1][f], &bfr[j >> 1][(j & 1) * 2]);
                }
            }
        }

        if ((t & (GRP1 - 1)) == (GRP1 - 1)) {
            #pragma unroll
            for (int f = 0; f < 4; ++f)
                #pragma unroll
                for (int j = 0; j < 4; ++j)
                    #pragma unroll
                    for (int q = 0; q < 4; ++q) {
                        racc[f][j][q] += acc[f][j][q];
                        acc[f][j][q] = 0.0f;
                    }
        }
    }

    #pragma unroll
    for (int f = 0; f < 4; ++f) {
        #pragma unroll
        for (int j = 0; j < 4; ++j) {
            const int nb = col0 + wn * 32 + j * 8 + (l & 3) * 2;
            #pragma unroll
            for (int h = 0; h < 2; ++h) {
                const int row = row0 + wm * 64 + f * 16 + h * 8 + (l >> 2);
                const float va = racc[f][j][2 * h];
                const float vb = racc[f][j][2 * h + 1];
                int ia = 0, ib = 0;
                #pragma unroll
                for (int q = 0; q < 15; ++q) {
                    ia += (va > s_bnd[q]) ? 1 : 0;
                    ib += (vb > s_bnd[q]) ? 1 : 0;
                }
                const size_t o = ((size_t)row * DIM_ + nb) >> 1;
                ((uint32_t*)Yh)[o] = s_cbh[ia] | (s_cbh[ib] << 16);
            }
        }
    }
}

// ---------------- GEMM2: single-product fp16 HMMA, BKH=64 + XOR swizzle -----
// 256 threads, 2x4 warp grid (64x32 warp tiles), NSTG=3 pipeline.
__global__ __launch_bounds__(256, 1)
void gemm2_kernel(const unsigned short* __restrict__ A, const unsigned short* __restrict__ B,
                  float* __restrict__ Cout)
{
    extern __shared__ char smem[];
    const uint32_t sb = smem_u32(smem);

    const int tid = threadIdx.x;
    const int w = tid >> 5, l = tid & 31;
    const int wm = w >> 2, wn = w & 3;          // 2x4 warp grid, warp tile 64x32
    const int row0 = blockIdx.y * BM;
    const int col0 = blockIdx.x * BN;

    const unsigned short* tbase[2] = {A + (size_t)row0 * DIM_, B + (size_t)col0 * DIM_};
    uint32_t goff[4], soff[4];
    #pragma unroll
    for (int i = 0; i < 4; ++i) {
        const int id = i * 256 + tid;
        const int r = id >> 3, c = id & 7;
        goff[i] = (uint32_t)(r * DIM_ + c * 8);
        soff[i] = (uint32_t)(r * 128 + ((c ^ (r & 7)) * 16));
    }

    auto load_chunk = [&](int ch, int st) {
        const int k0 = ch * BKH1;
        const uint32_t stg = sb + st * STG2B;
        #pragma unroll
        for (int t = 0; t < 2; ++t)
            #pragma unroll
            for (int i = 0; i < 4; ++i)
                cpasync16(stg + t * TILE1B + soff[i], tbase[t] + goff[i] + k0);
        CP_COMMIT();
    };

    float acc[4][4][4];
    #pragma unroll
    for (int f = 0; f < 4; ++f)
        #pragma unroll
        for (int j = 0; j < 4; ++j)
            #pragma unroll
            for (int q = 0; q < 4; ++q) acc[f][j][q] = 0.0f;

    const int lxor = l & 7;
    const int a_row = wm * 64 + (l & 15);
    const int a_c0  = l >> 4;
    const int b_row = wn * 32 + (l & 7) + ((l >> 4) & 1) * 8;
    const int b_c0  = (l >> 3) & 1;

    load_chunk(0, 0);
    load_chunk(1, 1);

    for (int t = 0; t < NCH1; ++t) {
        const int st = t % 3;
        CP_WAIT1();
        __syncthreads();
        if (t + 2 < NCH1) load_chunk(t + 2, (t + 2) % 3);
        else              CP_COMMIT();

        const uint32_t base = sb + st * STG2B;
        #pragma unroll
        for (int ks = 0; ks < 4; ++ks) {
            uint32_t afr[4][4];
            #pragma unroll
            for (int f = 0; f < 4; ++f)
                ldsm4(afr[f], base
                      + (a_row + f * 16) * 128 + (((a_c0 + 2 * ks) ^ lxor) * 16));
            uint32_t bfr[2][4];
            #pragma unroll
            for (int p = 0; p < 2; ++p)
                ldsm4(bfr[p], base + TILE1B
                      + (b_row + p * 16) * 128 + (((b_c0 + 2 * ks) ^ lxor) * 16));
            #pragma unroll
            for (int f = 0; f < 4; ++f)
                #pragma unroll
                for (int j = 0; j < 4; ++j)
                    mma16816(acc[f][j], afr[f], &bfr[j >> 1][(j & 1) * 2]);
        }
    }

    // ---- epilogue: out = acc * 2^-28 ---------------------------------------
    // m = wm*64 + f*16 + h*8 + l/4 ; n = wn*32 + j*8 + 2*(l&3) + (q&1)
    #pragma unroll
    for (int f = 0; f < 4; ++f) {
        #pragma unroll
        for (int j = 0; j < 4; ++j) {
            const int nb = col0 + wn * 32 + j * 8 + (l & 3) * 2;
            #pragma unroll
            for (int h = 0; h < 2; ++h) {
                const int row = row0 + wm * 64 + f * 16 + h * 8 + (l >> 2);
                const float s = 1.0f / 268435456.0f;   // 2^-28
                *(float2*)(Cout + (size_t)row * DIM_ + nb) =
                    make_float2(acc[f][j][2 * h] * s, acc[f][j][2 * h + 1] * s);
            }
        }
    }
}

// ---------------- host ------------------------------------------------------
extern "C" void kernel_launch(void* const* d_in, const int* in_sizes, int n_in,
                              void* d_out, int out_size)
{
    const float* x  = (const float*)d_in[0];
    const float* Pi = (const float*)d_in[1];
    const float* cb = (const float*)d_in[2];
    float* out = (float*)d_out;

    unsigned short *x0, *x1, *p0, *p1, *th, *yh;
    cudaGetSymbolAddress((void**)&x0, g_x0);
    cudaGetSymbolAddress((void**)&x1, g_x1);
    cudaGetSymbolAddress((void**)&p0, g_p0);
    cudaGetSymbolAddress((void**)&p1, g_p1);
    cudaGetSymbolAddress((void**)&th, g_th);
    cudaGetSymbolAddress((void**)&yh, g_yh);

    const size_t N = (size_t)DIM_ * DIM_;
    const int smem1 = NSTG1 * STG1B;  // 196608
    const int smem2 = NSTG1 * STG2B;  // 98304
    cudaFuncSetAttribute(gemm1_kernel,
                         cudaFuncAttributeMaxDynamicSharedMemorySize, smem1);
    cudaFuncSetAttribute(gemm2_kernel,
                         cudaFuncAttributeMaxDynamicSharedMemorySize, smem2);

    // 1) prep: 2^12 x -> (x0,x1) ; 2^16 Pi -> (p0,p1) ; fp16(2^16 Pi^T) -> th
    split2_kernel<4096><<<(int)(N / 4 / 256), 256>>>((const float4*)x,
                                                     (uint32_t*)x0, (uint32_t*)x1);
    split2_kernel<65536><<<(int)(N / 4 / 256), 256>>>((const float4*)Pi,
                                                      (uint32_t*)p0, (uint32_t*)p1);
    transhalf_kernel<<<dim3(DIM_ / 32, DIM_ / 32), dim3(32, 8)>>>(Pi, th);

    dim3 grid(DIM_ / BN, DIM_ / BM);
    // 2) GEMM1 (3-product, BKH1=64, GRP1=2 register drain) + quantize -> yh
    gemm1_kernel<<<grid, 256, smem1>>>(x0, x1, p0, p1, cb, yh);
    // 3) GEMM2 (single product, BKH=64): out = (2^12 y~ @ 2^16 Pi) * 2^-28
    gemm2_kernel<<<grid, 256, smem2>>>(yh, th, out);
}

// round 15
// speedup vs baseline: 2.0795x; 1.0333x over previous
#include <cuda_runtime.h>
#include <cuda_fp16.h>
#include <cstdint>

#define DIM_ 4096
#define BM 128
#define BN 128            // GEMM2 CTA tile N
#define BN1 64            // GEMM1 CTA tile N (2 CTAs/SM config)

// ---- shared geometry: BKH=64, 128B rows, XOR-swizzled ----------------------
#define BKH1 64
#define NCH1 (DIM_ / BKH1)    // 64 chunks
#define GRP1 2                // GEMM1: drain every 2 chunks = 128 k
#define TILE1B (BM * 128)     // 16384 B (128-row tile)
#define TILEB1B (BN1 * 128)   // 8192 B  (64-row tile)
#define STG1B (2 * TILE1B + 2 * TILEB1B)  // GEMM1 stage: A0,A1,B0,B1 = 49152 B
#define NSTG1G1 2             // GEMM1: 2 stages (2 CTAs/SM)
#define STG2B (2 * TILE1B)    // GEMM2 stage: A,B = 32768 B
#define NSTG2 3

// Scales (exact powers of 2): x*2^12 -> (x0,x1); Pi*2^16 -> (p0,p1);
// y~ stored fp16(c*2^12); Pi^T stored fp16(Pi^T*2^16).
// GEMM1 acc = 2^28*y, bnd*2^27. GEMM2 acc = 2^28*x~, out *2^-28.

// ---------------- scratch (allocation-free rule: __device__ globals) --------
__device__ unsigned short g_x0[(size_t)DIM_ * DIM_];
__device__ unsigned short g_x1[(size_t)DIM_ * DIM_];
__device__ unsigned short g_p0[(size_t)DIM_ * DIM_];
__device__ unsigned short g_p1[(size_t)DIM_ * DIM_];
__device__ unsigned short g_th[(size_t)DIM_ * DIM_];   // fp16(2^16 Pi^T), K-major
__device__ unsigned short g_yh[(size_t)DIM_ * DIM_];   // fp16(2^12 y~)

// ---------------- PTX helpers -----------------------------------------------
__device__ __forceinline__ uint32_t smem_u32(const void* p) {
    uint32_t a;
    asm("{ .reg .u64 t; cvta.to.shared.u64 t, %1; cvt.u32.u64 %0, t; }" : "=r"(a) : "l"(p));
    return a;
}
__device__ __forceinline__ void cpasync16(uint32_t sa, const void* g) {
    asm volatile("cp.async.cg.shared.global [%0], [%1], 16;" :: "r"(sa), "l"(g));
}
__device__ __forceinline__ void ldsm4(uint32_t* r, uint32_t a) {
    asm volatile("ldmatrix.sync.aligned.m8n8.x4.shared.b16 {%0,%1,%2,%3}, [%4];"
                 : "=r"(r[0]), "=r"(r[1]), "=r"(r[2]), "=r"(r[3]) : "r"(a));
}
__device__ __forceinline__ void mma16816(float* d, const uint32_t* a, const uint32_t* b) {
    asm volatile("mma.sync.aligned.m16n8k16.row.col.f32.f16.f16.f32 "
                 "{%0,%1,%2,%3}, {%4,%5,%6,%7}, {%8,%9}, {%0,%1,%2,%3};"
                 : "+f"(d[0]), "+f"(d[1]), "+f"(d[2]), "+f"(d[3])
                 : "r"(a[0]), "r"(a[1]), "r"(a[2]), "r"(a[3]), "r"(b[0]), "r"(b[1]));
}
#define CP_COMMIT() asm volatile("cp.async.commit_group;" ::: "memory")
#define CP_WAIT1()  asm volatile("cp.async.wait_group 1;" ::: "memory")

// ---------------- fp16 2-split (Markidis, pre-scaled) -----------------------
__device__ __forceinline__ void hsplit2(float v, unsigned short& b0, unsigned short& b1) {
    __half h0 = __float2half_rn(v);
    float r = v - __half2float(h0);
    __half h1 = __float2half_rn(r);
    b0 = *reinterpret_cast<unsigned short*>(&h0);
    b1 = *reinterpret_cast<unsigned short*>(&h1);
}

template<int SCALE>
__global__ void split2_kernel(const float4* __restrict__ in,
                              uint32_t* __restrict__ o0, uint32_t* __restrict__ o1) {
    int i = blockIdx.x * blockDim.x + threadIdx.x;
    float4 v = in[i];
    const float s = (float)SCALE;
    unsigned short a0[4], a1[4];
    hsplit2(v.x * s, a0[0], a1[0]);
    hsplit2(v.y * s, a0[1], a1[1]);
    hsplit2(v.z * s, a0[2], a1[2]);
    hsplit2(v.w * s, a0[3], a1[3]);
    o0[2 * i] = a0[0] | ((uint32_t)a0[1] << 16); o0[2 * i + 1] = a0[2] | ((uint32_t)a0[3] << 16);
    o1[2 * i] = a1[0] | ((uint32_t)a1[1] << 16); o1[2 * i + 1] = a1[2] | ((uint32_t)a1[3] << 16);
}

// Pi -> fp16(2^16 Pi^T), tiled transpose
__global__ void transhalf_kernel(const float* __restrict__ Pi,
                                 unsigned short* __restrict__ th) {
    __shared__ float tile[32][33];
    int tx = threadIdx.x, ty = threadIdx.y;
    int c0 = blockIdx.x * 32, r0 = blockIdx.y * 32;
    #pragma unroll
    for (int i = 0; i < 4; ++i)
        tile[ty + 8 * i][tx] = Pi[(size_t)(r0 + ty + 8 * i) * DIM_ + c0 + tx];
    __syncthreads();
    #pragma unroll
    for (int i = 0; i < 4; ++i) {
        __half h = __float2half_rn(tile[tx][ty + 8 * i] * 65536.0f);
        th[(size_t)(c0 + ty + 8 * i) * DIM_ + r0 + tx] = *reinterpret_cast<unsigned short*>(&h);
    }
}

// ---------------- GEMM1: 3-product split HMMA + quantize, 2 CTAs/SM ---------
// 256 threads, 2x4 warp grid (64x16 warp tiles), CTA tile 128x64,
// 2-stage pipeline, register RZ-drain every GRP1 chunks.
__global__ __launch_bounds__(256, 2)
void gemm1_kernel(const unsigned short* __restrict__ A0, const unsigned short* __restrict__ A1,
                  const unsigned short* __restrict__ Bm0, const unsigned short* __restrict__ Bm1,
                  const float* __restrict__ cb, unsigned short* __restrict__ Yh)
{
    extern __shared__ char smem[];
    const uint32_t sb = smem_u32(smem);
    __shared__ float s_bnd[15];        // 2^27 * (c_i + c_{i+1})
    __shared__ uint32_t s_cbh[16];     // fp16(2^12 * codebook), low 16 bits

    const int tid = threadIdx.x;
    const int w = tid >> 5, l = tid & 31;
    const int wm = w >> 2, wn = w & 3;          // 2x4 warp grid, warp tile 64x16
    const int row0 = blockIdx.y * BM;
    const int col0 = blockIdx.x * BN1;

    if (tid < 16) {
        __half h = __float2half_rn(cb[tid] * 4096.0f);
        s_cbh[tid] = (uint32_t)(*reinterpret_cast<unsigned short*>(&h));
    }
    if (tid < 15) s_bnd[tid] = (cb[tid] + cb[tid + 1]) * 134217728.0f;  // 2^27

    const unsigned short* abase[2] = {A0 + (size_t)row0 * DIM_, A1 + (size_t)row0 * DIM_};
    const unsigned short* bbase[2] = {Bm0 + (size_t)col0 * DIM_, Bm1 + (size_t)col0 * DIM_};

    // A tiles: 1024 x16B each -> 4/thread ; B tiles: 512 x16B -> 2/thread
    uint32_t goffA[4], soffA[4], goffB[2], soffB[2];
    #pragma unroll
    for (int i = 0; i < 4; ++i) {
        const int id = i * 256 + tid;
        const int r = id >> 3, c = id & 7;
        goffA[i] = (uint32_t)(r * DIM_ + c * 8);
        soffA[i] = (uint32_t)(r * 128 + ((c ^ (r & 7)) * 16));
    }
    #pragma unroll
    for (int i = 0; i < 2; ++i) {
        const int id = i * 256 + tid;
        const int r = id >> 3, c = id & 7;
        goffB[i] = (uint32_t)(r * DIM_ + c * 8);
        soffB[i] = (uint32_t)(r * 128 + ((c ^ (r & 7)) * 16));
    }

    auto load_chunk = [&](int ch, int st) {
        const int k0 = ch * BKH1;
        const uint32_t stg = sb + st * STG1B;
        #pragma unroll
        for (int t = 0; t < 2; ++t)
            #pragma unroll
            for (int i = 0; i < 4; ++i)
                cpasync16(stg + t * TILE1B + soffA[i], abase[t] + goffA[i] + k0);
        #pragma unroll
        for (int t = 0; t < 2; ++t)
            #pragma unroll
            for (int i = 0; i < 2; ++i)
                cpasync16(stg + 2 * TILE1B + t * TILEB1B + soffB[i], bbase[t] + goffB[i] + k0);
        CP_COMMIT();
    };

    float acc[4][2][4];     // RZ-chained partials (reset every GRP1 chunks)
    float racc[4][2][4];    // RN register totals
    #pragma unroll
    for (int f = 0; f < 4; ++f)
        #pragma unroll
        for (int j = 0; j < 2; ++j)
            #pragma unroll
            for (int q = 0; q < 4; ++q) { acc[f][j][q] = 0.0f; racc[f][j][q] = 0.0f; }

    const int lxor = l & 7;
    const int a_row = wm * 64 + (l & 15);
    const int a_c0  = l >> 4;
    const int b_row = wn * 16 + (l & 7) + ((l >> 4) & 1) * 8;
    const int b_c0  = (l >> 3) & 1;

    load_chunk(0, 0);

    for (int t = 0; t < NCH1; ++t) {
        __syncthreads();                 // overwrite target (stage (t+1)&1) free
        if (t + 1 < NCH1) load_chunk(t + 1, (t + 1) & 1);
        else              CP_COMMIT();   // empty group keeps pending-count exact
        CP_WAIT1();                      // group t complete
        __syncthreads();                 // visibility of stage t to all warps

        const uint32_t base = sb + (t & 1) * STG1B;
        #pragma unroll
        for (int ks = 0; ks < 4; ++ks) {
            uint32_t afr[2][4][4];
            #pragma unroll
            for (int s = 0; s < 2; ++s)
                #pragma unroll
                for (int f = 0; f < 4; ++f)
                    ldsm4(afr[s][f], base + s * TILE1B
                          + (a_row + f * 16) * 128 + (((a_c0 + 2 * ks) ^ lxor) * 16));

            #pragma unroll
            for (int sB = 0; sB < 2; ++sB) {
                uint32_t bfr[4];
                ldsm4(bfr, base + 2 * TILE1B + sB * TILEB1B
                      + b_row * 128 + (((b_c0 + 2 * ks) ^ lxor) * 16));
                // sB==0: a0*b0 + a1*b0 ; sB==1: a0*b1
                #pragma unroll
                for (int f = 0; f < 4; ++f)
                    #pragma unroll
                    for (int j = 0; j < 2; ++j)
                        mma16816(acc[f][j], afr[0][f], &bfr[j * 2]);
                if (sB == 0) {
                    #pragma unroll
                    for (int f = 0; f < 4; ++f)
                        #pragma unroll
                        for (int j = 0; j < 2; ++j)
                            mma16816(acc[f][j], afr[1][f], &bfr[j * 2]);
                }
            }
        }

        // group drain: RN-add partials into register totals, reset RZ chain
        if ((t & (GRP1 - 1)) == (GRP1 - 1)) {
            #pragma unroll
            for (int f = 0; f < 4; ++f)
                #pragma unroll
                for (int j = 0; j < 2; ++j)
                    #pragma unroll
                    for (int q = 0; q < 4; ++q) {
                        racc[f][j][q] += acc[f][j][q];
                        acc[f][j][q] = 0.0f;
                    }
        }
    }

    // ---- epilogue: quantize -> single fp16 y~ -------------------------------
    // m = wm*64 + f*16 + h*8 + l/4 ; n = wn*16 + j*8 + 2*(l&3) + (q&1)
    #pragma unroll
    for (int f = 0; f < 4; ++f) {
        #pragma unroll
        for (int j = 0; j < 2; ++j) {
            const int nb = col0 + wn * 16 + j * 8 + (l & 3) * 2;
            #pragma unroll
            for (int h = 0; h < 2; ++h) {
                const int row = row0 + wm * 64 + f * 16 + h * 8 + (l >> 2);
                const float va = racc[f][j][2 * h];
                const float vb = racc[f][j][2 * h + 1];
                int ia = 0, ib = 0;
                #pragma unroll
                for (int q = 0; q < 15; ++q) {
                    ia += (va > s_bnd[q]) ? 1 : 0;
                    ib += (vb > s_bnd[q]) ? 1 : 0;
                }
                const size_t o = ((size_t)row * DIM_ + nb) >> 1;
                ((uint32_t*)Yh)[o] = s_cbh[ia] | (s_cbh[ib] << 16);
            }
        }
    }
}

// ---------------- GEMM2: single-product fp16 HMMA (unchanged R13) -----------
__global__ __launch_bounds__(256, 1)
void gemm2_kernel(const unsigned short* __restrict__ A, const unsigned short* __restrict__ B,
                  float* __restrict__ Cout)
{
    extern __shared__ char smem[];
    const uint32_t sb = smem_u32(smem);

    const int tid = threadIdx.x;
    const int w = tid >> 5, l = tid & 31;
    const int wm = w >> 2, wn = w & 3;          // 2x4 warp grid, warp tile 64x32
    const int row0 = blockIdx.y * BM;
    const int col0 = blockIdx.x * BN;

    const unsigned short* tbase[2] = {A + (size_t)row0 * DIM_, B + (size_t)col0 * DIM_};
    uint32_t goff[4], soff[4];
    #pragma unroll
    for (int i = 0; i < 4; ++i) {
        const int id = i * 256 + tid;
        const int r = id >> 3, c = id & 7;
        goff[i] = (uint32_t)(r * DIM_ + c * 8);
        soff[i] = (uint32_t)(r * 128 + ((c ^ (r & 7)) * 16));
    }

    auto load_chunk = [&](int ch, int st) {
        const int k0 = ch * BKH1;
        const uint32_t stg = sb + st * STG2B;
        #pragma unroll
        for (int t = 0; t < 2; ++t)
            #pragma unroll
            for (int i = 0; i < 4; ++i)
                cpasync16(stg + t * TILE1B + soff[i], tbase[t] + goff[i] + k0);
        CP_COMMIT();
    };

    float acc[4][4][4];
    #pragma unroll
    for (int f = 0; f < 4; ++f)
        #pragma unroll
        for (int j = 0; j < 4; ++j)
            #pragma unroll
            for (int q = 0; q < 4; ++q) acc[f][j][q] = 0.0f;

    const int lxor = l & 7;
    const int a_row = wm * 64 + (l & 15);
    const int a_c0  = l >> 4;
    const int b_row = wn * 32 + (l & 7) + ((l >> 4) & 1) * 8;
    const int b_c0  = (l >> 3) & 1;

    load_chunk(0, 0);
    load_chunk(1, 1);

    for (int t = 0; t < NCH1; ++t) {
        const int st = t % 3;
        CP_WAIT1();
        __syncthreads();
        if (t + 2 < NCH1) load_chunk(t + 2, (t + 2) % 3);
        else              CP_COMMIT();

        const uint32_t base = sb + st * STG2B;
        #pragma unroll
        for (int ks = 0; ks < 4; ++ks) {
            uint32_t afr[4][4];
            #pragma unroll
            for (int f = 0; f < 4; ++f)
                ldsm4(afr[f], base
                      + (a_row + f * 16) * 128 + (((a_c0 + 2 * ks) ^ lxor) * 16));
            uint32_t bfr[2][4];
            #pragma unroll
            for (int p = 0; p < 2; ++p)
                ldsm4(bfr[p], base + TILE1B
                      + (b_row + p * 16) * 128 + (((b_c0 + 2 * ks) ^ lxor) * 16));
            #pragma unroll
            for (int f = 0; f < 4; ++f)
                #pragma unroll
                for (int j = 0; j < 4; ++j)
                    mma16816(acc[f][j], afr[f], &bfr[j >> 1][(j & 1) * 2]);
        }
    }

    // ---- epilogue: out = acc * 2^-28 ---------------------------------------
    #pragma unroll
    for (int f = 0; f < 4; ++f) {
        #pragma unroll
        for (int j = 0; j < 4; ++j) {
            const int nb = col0 + wn * 32 + j * 8 + (l & 3) * 2;
            #pragma unroll
            for (int h = 0; h < 2; ++h) {
                const int row = row0 + wm * 64 + f * 16 + h * 8 + (l >> 2);
                const float s = 1.0f / 268435456.0f;   // 2^-28
                *(float2*)(Cout + (size_t)row * DIM_ + nb) =
                    make_float2(acc[f][j][2 * h] * s, acc[f][j][2 * h + 1] * s);
            }
        }
    }
}

// ---------------- host ------------------------------------------------------
extern "C" void kernel_launch(void* const* d_in, const int* in_sizes, int n_in,
                              void* d_out, int out_size)
{
    const float* x  = (const float*)d_in[0];
    const float* Pi = (const float*)d_in[1];
    const float* cb = (const float*)d_in[2];
    float* out = (float*)d_out;

    unsigned short *x0, *x1, *p0, *p1, *th, *yh;
    cudaGetSymbolAddress((void**)&x0, g_x0);
    cudaGetSymbolAddress((void**)&x1, g_x1);
    cudaGetSymbolAddress((void**)&p0, g_p0);
    cudaGetSymbolAddress((void**)&p1, g_p1);
    cudaGetSymbolAddress((void**)&th, g_th);
    cudaGetSymbolAddress((void**)&yh, g_yh);

    const size_t N = (size_t)DIM_ * DIM_;
    const int smem1 = NSTG1G1 * STG1B;  // 98304 (x2 CTAs/SM = 196608)
    const int smem2 = NSTG2 * STG2B;    // 98304
    cudaFuncSetAttribute(gemm1_kernel,
                         cudaFuncAttributeMaxDynamicSharedMemorySize, smem1);
    cudaFuncSetAttribute(gemm2_kernel,
                         cudaFuncAttributeMaxDynamicSharedMemorySize, smem2);

    // 1) prep: 2^12 x -> (x0,x1) ; 2^16 Pi -> (p0,p1) ; fp16(2^16 Pi^T) -> th
    split2_kernel<4096><<<(int)(N / 4 / 256), 256>>>((const float4*)x,
                                                     (uint32_t*)x0, (uint32_t*)x1);
    split2_kernel<65536><<<(int)(N / 4 / 256), 256>>>((const float4*)Pi,
                                                      (uint32_t*)p0, (uint32_t*)p1);
    transhalf_kernel<<<dim3(DIM_ / 32, DIM_ / 32), dim3(32, 8)>>>(Pi, th);

    // 2) GEMM1 (3-product, CTA 128x64, 2 CTAs/SM) + quantize -> yh
    dim3 grid1(DIM_ / BN1, DIM_ / BM);
    gemm1_kernel<<<grid1, 256, smem1>>>(x0, x1, p0, p1, cb, yh);
    // 3) GEMM2 (single product, CTA 128x128): out = (2^12 y~ @ 2^16 Pi) * 2^-28
    dim3 grid2(DIM_ / BN, DIM_ / BM);
    gemm2_kernel<<<grid2, 256, smem2>>>(yh, th, out);
}

// round 16
// speedup vs baseline: 2.1115x; 1.0154x over previous
#include <cuda_runtime.h>
#include <cuda_fp16.h>
#include <cstdint>

#define DIM_ 4096
#define BM 128
#define BN 128            // GEMM2 CTA tile N
#define BN1 64            // GEMM1 CTA tile N (2 CTAs/SM config)

// ---- shared geometry: BKH=64, 128B rows, XOR-swizzled ----------------------
#define BKH1 64
#define NCH1 (DIM_ / BKH1)    // 64 chunks
#define GRP1 2                // GEMM1: drain every 2 chunks = 128 k
#define TILE1B (BM * 128)     // 16384 B (128-row tile)
#define TILEB1B (BN1 * 128)   // 8192 B  (64-row tile)
#define STG1B (2 * TILE1B + 2 * TILEB1B)  // GEMM1 stage: A0,A1,B0,B1 = 49152 B
#define NSTG1G1 2             // GEMM1: 2 stages (2 CTAs/SM)
#define STG2B (2 * TILE1B)    // GEMM2 stage: A,B = 32768 B
#define NSTG2 3

// Scales (exact powers of 2): x*2^12 -> (x0,x1); Pi*2^16 -> (p0,p1);
// y~ stored fp16(c*2^12); Pi^T stored fp16(Pi^T*2^16).
// GEMM1 acc = 2^28*y, bnd*2^27. GEMM2 acc = 2^28*x~, out *2^-28.

// ---------------- scratch (allocation-free rule: __device__ globals) --------
__device__ unsigned short g_x0[(size_t)DIM_ * DIM_];
__device__ unsigned short g_x1[(size_t)DIM_ * DIM_];
__device__ unsigned short g_p0[(size_t)DIM_ * DIM_];
__device__ unsigned short g_p1[(size_t)DIM_ * DIM_];
__device__ unsigned short g_th[(size_t)DIM_ * DIM_];   // fp16(2^16 Pi^T), K-major
__device__ unsigned short g_yh[(size_t)DIM_ * DIM_];   // fp16(2^12 y~)

// ---------------- PTX helpers -----------------------------------------------
__device__ __forceinline__ uint32_t smem_u32(const void* p) {
    uint32_t a;
    asm("{ .reg .u64 t; cvta.to.shared.u64 t, %1; cvt.u32.u64 %0, t; }" : "=r"(a) : "l"(p));
    return a;
}
__device__ __forceinline__ void cpasync16(uint32_t sa, const void* g) {
    asm volatile("cp.async.cg.shared.global [%0], [%1], 16;" :: "r"(sa), "l"(g));
}
__device__ __forceinline__ void ldsm4(uint32_t* r, uint32_t a) {
    asm volatile("ldmatrix.sync.aligned.m8n8.x4.shared.b16 {%0,%1,%2,%3}, [%4];"
                 : "=r"(r[0]), "=r"(r[1]), "=r"(r[2]), "=r"(r[3]) : "r"(a));
}
__device__ __forceinline__ void mma16816(float* d, const uint32_t* a, const uint32_t* b) {
    asm volatile("mma.sync.aligned.m16n8k16.row.col.f32.f16.f16.f32 "
                 "{%0,%1,%2,%3}, {%4,%5,%6,%7}, {%8,%9}, {%0,%1,%2,%3};"
                 : "+f"(d[0]), "+f"(d[1]), "+f"(d[2]), "+f"(d[3])
                 : "r"(a[0]), "r"(a[1]), "r"(a[2]), "r"(a[3]), "r"(b[0]), "r"(b[1]));
}
#define CP_COMMIT() asm volatile("cp.async.commit_group;" ::: "memory")
#define CP_WAIT1()  asm volatile("cp.async.wait_group 1;" ::: "memory")

// ---------------- fp16 2-split (Markidis, pre-scaled) -----------------------
__device__ __forceinline__ void hsplit2(float v, unsigned short& b0, unsigned short& b1) {
    __half h0 = __float2half_rn(v);
    float r = v - __half2float(h0);
    __half h1 = __float2half_rn(r);
    b0 = *reinterpret_cast<unsigned short*>(&h0);
    b1 = *reinterpret_cast<unsigned short*>(&h1);
}

template<int SCALE>
__global__ void split2_kernel(const float4* __restrict__ in,
                              uint32_t* __restrict__ o0, uint32_t* __restrict__ o1) {
    int i = blockIdx.x * blockDim.x + threadIdx.x;
    float4 v = in[i];
    const float s = (float)SCALE;
    unsigned short a0[4], a1[4];
    hsplit2(v.x * s, a0[0], a1[0]);
    hsplit2(v.y * s, a0[1], a1[1]);
    hsplit2(v.z * s, a0[2], a1[2]);
    hsplit2(v.w * s, a0[3], a1[3]);
    o0[2 * i] = a0[0] | ((uint32_t)a0[1] << 16); o0[2 * i + 1] = a0[2] | ((uint32_t)a0[3] << 16);
    o1[2 * i] = a1[0] | ((uint32_t)a1[1] << 16); o1[2 * i + 1] = a1[2] | ((uint32_t)a1[3] << 16);
}

// Pi -> fp16(2^16 Pi^T), tiled transpose
__global__ void transhalf_kernel(const float* __restrict__ Pi,
                                 unsigned short* __restrict__ th) {
    __shared__ float tile[32][33];
    int tx = threadIdx.x, ty = threadIdx.y;
    int c0 = blockIdx.x * 32, r0 = blockIdx.y * 32;
    #pragma unroll
    for (int i = 0; i < 4; ++i)
        tile[ty + 8 * i][tx] = Pi[(size_t)(r0 + ty + 8 * i) * DIM_ + c0 + tx];
    __syncthreads();
    #pragma unroll
    for (int i = 0; i < 4; ++i) {
        __half h = __float2half_rn(tile[tx][ty + 8 * i] * 65536.0f);
        th[(size_t)(c0 + ty + 8 * i) * DIM_ + r0 + tx] = *reinterpret_cast<unsigned short*>(&h);
    }
}

// ---------------- GEMM1: 3-product split HMMA + quantize, 2 CTAs/SM ---------
// 256 threads, 4x2 warp grid (32x32 warp tiles), CTA tile 128x64,
// 2-stage pipeline, register RZ-drain every GRP1 chunks.
__global__ __launch_bounds__(256, 2)
void gemm1_kernel(const unsigned short* __restrict__ A0, const unsigned short* __restrict__ A1,
                  const unsigned short* __restrict__ Bm0, const unsigned short* __restrict__ Bm1,
                  const float* __restrict__ cb, unsigned short* __restrict__ Yh)
{
    extern __shared__ char smem[];
    const uint32_t sb = smem_u32(smem);
    __shared__ float s_bnd[15];        // 2^27 * (c_i + c_{i+1})
    __shared__ uint32_t s_cbh[16];     // fp16(2^12 * codebook), low 16 bits

    const int tid = threadIdx.x;
    const int w = tid >> 5, l = tid & 31;
    const int wm = w & 3, wn = w >> 2;          // 4x2 warp grid, warp tile 32x32
    const int row0 = blockIdx.y * BM;
    const int col0 = blockIdx.x * BN1;

    if (tid < 16) {
        __half h = __float2half_rn(cb[tid] * 4096.0f);
        s_cbh[tid] = (uint32_t)(*reinterpret_cast<unsigned short*>(&h));
    }
    if (tid < 15) s_bnd[tid] = (cb[tid] + cb[tid + 1]) * 134217728.0f;  // 2^27

    const unsigned short* abase[2] = {A0 + (size_t)row0 * DIM_, A1 + (size_t)row0 * DIM_};
    const unsigned short* bbase[2] = {Bm0 + (size_t)col0 * DIM_, Bm1 + (size_t)col0 * DIM_};

    // A tiles: 1024 x16B each -> 4/thread ; B tiles: 512 x16B -> 2/thread
    uint32_t goffA[4], soffA[4], goffB[2], soffB[2];
    #pragma unroll
    for (int i = 0; i < 4; ++i) {
        const int id = i * 256 + tid;
        const int r = id >> 3, c = id & 7;
        goffA[i] = (uint32_t)(r * DIM_ + c * 8);
        soffA[i] = (uint32_t)(r * 128 + ((c ^ (r & 7)) * 16));
    }
    #pragma unroll
    for (int i = 0; i < 2; ++i) {
        const int id = i * 256 + tid;
        const int r = id >> 3, c = id & 7;
        goffB[i] = (uint32_t)(r * DIM_ + c * 8);
        soffB[i] = (uint32_t)(r * 128 + ((c ^ (r & 7)) * 16));
    }

    auto load_chunk = [&](int ch, int st) {
        const int k0 = ch * BKH1;
        const uint32_t stg = sb + st * STG1B;
        #pragma unroll
        for (int t = 0; t < 2; ++t)
            #pragma unroll
            for (int i = 0; i < 4; ++i)
                cpasync16(stg + t * TILE1B + soffA[i], abase[t] + goffA[i] + k0);
        #pragma unroll
        for (int t = 0; t < 2; ++t)
            #pragma unroll
            for (int i = 0; i < 2; ++i)
                cpasync16(stg + 2 * TILE1B + t * TILEB1B + soffB[i], bbase[t] + goffB[i] + k0);
        CP_COMMIT();
    };

    float acc[2][4][4];     // RZ-chained partials (reset every GRP1 chunks)
    float racc[2][4][4];    // RN register totals
    #pragma unroll
    for (int f = 0; f < 2; ++f)
        #pragma unroll
        for (int j = 0; j < 4; ++j)
            #pragma unroll
            for (int q = 0; q < 4; ++q) { acc[f][j][q] = 0.0f; racc[f][j][q] = 0.0f; }

    const int lxor = l & 7;
    const int a_row = wm * 32 + (l & 15);
    const int a_c0  = l >> 4;
    const int b_row = wn * 32 + (l & 7) + ((l >> 4) & 1) * 8;
    const int b_c0  = (l >> 3) & 1;

    load_chunk(0, 0);

    for (int t = 0; t < NCH1; ++t) {
        __syncthreads();                 // overwrite target (stage (t+1)&1) free
        if (t + 1 < NCH1) load_chunk(t + 1, (t + 1) & 1);
        else              CP_COMMIT();   // empty group keeps pending-count exact
        CP_WAIT1();                      // group t complete
        __syncthreads();                 // visibility of stage t to all warps

        const uint32_t base = sb + (t & 1) * STG1B;
        #pragma unroll
        for (int ks = 0; ks < 4; ++ks) {
            uint32_t afr[2][2][4];              // [split][mfrag 16-rows][4]
            #pragma unroll
            for (int s = 0; s < 2; ++s)
                #pragma unroll
                for (int f = 0; f < 2; ++f)
                    ldsm4(afr[s][f], base + s * TILE1B
                          + (a_row + f * 16) * 128 + (((a_c0 + 2 * ks) ^ lxor) * 16));

            #pragma unroll
            for (int sB = 0; sB < 2; ++sB) {
                uint32_t bfr[2][4];
                #pragma unroll
                for (int p = 0; p < 2; ++p)
                    ldsm4(bfr[p], base + 2 * TILE1B + sB * TILEB1B
                          + (b_row + p * 16) * 128 + (((b_c0 + 2 * ks) ^ lxor) * 16));
                // sB==0: a0*b0 + a1*b0 ; sB==1: a0*b1
                #pragma unroll
                for (int f = 0; f < 2; ++f)
                    #pragma unroll
                    for (int j = 0; j < 4; ++j)
                        mma16816(acc[f][j], afr[0][f], &bfr[j >> 1][(j & 1) * 2]);
                if (sB == 0) {
                    #pragma unroll
                    for (int f = 0; f < 2; ++f)
                        #pragma unroll
                        for (int j = 0; j < 4; ++j)
                            mma16816(acc[f][j], afr[1][f], &bfr[j >> 1][(j & 1) * 2]);
                }
            }
        }

        // group drain: RN-add partials into register totals, reset RZ chain
        if ((t & (GRP1 - 1)) == (GRP1 - 1)) {
            #pragma unroll
            for (int f = 0; f < 2; ++f)
                #pragma unroll
                for (int j = 0; j < 4; ++j)
                    #pragma unroll
                    for (int q = 0; q < 4; ++q) {
                        racc[f][j][q] += acc[f][j][q];
                        acc[f][j][q] = 0.0f;
                    }
        }
    }

    // ---- epilogue: quantize -> single fp16 y~ -------------------------------
    // m = wm*32 + f*16 + h*8 + l/4 ; n = wn*32 + j*8 + 2*(l&3) + (q&1)
    #pragma unroll
    for (int f = 0; f < 2; ++f) {
        #pragma unroll
        for (int j = 0; j < 4; ++j) {
            const int nb = col0 + wn * 32 + j * 8 + (l & 3) * 2;
            #pragma unroll
            for (int h = 0; h < 2; ++h) {
                const int row = row0 + wm * 32 + f * 16 + h * 8 + (l >> 2);
                const float va = racc[f][j][2 * h];
                const float vb = racc[f][j][2 * h + 1];
                int ia = 0, ib = 0;
                #pragma unroll
                for (int q = 0; q < 15; ++q) {
                    ia += (va > s_bnd[q]) ? 1 : 0;
                    ib += (vb > s_bnd[q]) ? 1 : 0;
                }
                const size_t o = ((size_t)row * DIM_ + nb) >> 1;
                ((uint32_t*)Yh)[o] = s_cbh[ia] | (s_cbh[ib] << 16);
            }
        }
    }
}

// ---------------- GEMM2: single-product fp16 HMMA (unchanged R13) -----------
__global__ __launch_bounds__(256, 1)
void gemm2_kernel(const unsigned short* __restrict__ A, const unsigned short* __restrict__ B,
                  float* __restrict__ Cout)
{
    extern __shared__ char smem[];
    const uint32_t sb = smem_u32(smem);

    const int tid = threadIdx.x;
    const int w = tid >> 5, l = tid & 31;
    const int wm = w >> 2, wn = w & 3;          // 2x4 warp grid, warp tile 64x32
    const int row0 = blockIdx.y * BM;
    const int col0 = blockIdx.x * BN;

    const unsigned short* tbase[2] = {A + (size_t)row0 * DIM_, B + (size_t)col0 * DIM_};
    uint32_t goff[4], soff[4];
    #pragma unroll
    for (int i = 0; i < 4; ++i) {
        const int id = i * 256 + tid;
        const int r = id >> 3, c = id & 7;
        goff[i] = (uint32_t)(r * DIM_ + c * 8);
        soff[i] = (uint32_t)(r * 128 + ((c ^ (r & 7)) * 16));
    }

    auto load_chunk = [&](int ch, int st) {
        const int k0 = ch * BKH1;
        const uint32_t stg = sb + st * STG2B;
        #pragma unroll
        for (int t = 0; t < 2; ++t)
            #pragma unroll
            for (int i = 0; i < 4; ++i)
                cpasync16(stg + t * TILE1B + soff[i], tbase[t] + goff[i] + k0);
        CP_COMMIT();
    };

    float acc[4][4][4];
    #pragma unroll
    for (int f = 0; f < 4; ++f)
        #pragma unroll
        for (int j = 0; j < 4; ++j)
            #pragma unroll
            for (int q = 0; q < 4; ++q) acc[f][j][q] = 0.0f;

    const int lxor = l & 7;
    const int a_row = wm * 64 + (l & 15);
    const int a_c0  = l >> 4;
    const int b_row = wn * 32 + (l & 7) + ((l >> 4) & 1) * 8;
    const int b_c0  = (l >> 3) & 1;

    load_chunk(0, 0);
    load_chunk(1, 1);

    for (int t = 0; t < NCH1; ++t) {
        const int st = t % 3;
        CP_WAIT1();
        __syncthreads();
        if (t + 2 < NCH1) load_chunk(t + 2, (t + 2) % 3);
        else              CP_COMMIT();

        const uint32_t base = sb + st * STG2B;
        #pragma unroll
        for (int ks = 0; ks < 4; ++ks) {
            uint32_t afr[4][4];
            #pragma unroll
            for (int f = 0; f < 4; ++f)
                ldsm4(afr[f], base
                      + (a_row + f * 16) * 128 + (((a_c0 + 2 * ks) ^ lxor) * 16));
            uint32_t bfr[2][4];
            #pragma unroll
            for (int p = 0; p < 2; ++p)
                ldsm4(bfr[p], base + TILE1B
                      + (b_row + p * 16) * 128 + (((b_c0 + 2 * ks) ^ lxor) * 16));
            #pragma unroll
            for (int f = 0; f < 4; ++f)
                #pragma unroll
                for (int j = 0; j < 4; ++j)
                    mma16816(acc[f][j], afr[f], &bfr[j >> 1][(j & 1) * 2]);
        }
    }

    // ---- epilogue: out = acc * 2^-28 ---------------------------------------
    #pragma unroll
    for (int f = 0; f < 4; ++f) {
        #pragma unroll
        for (int j = 0; j < 4; ++j) {
            const int nb = col0 + wn * 32 + j * 8 + (l & 3) * 2;
            #pragma unroll
            for (int h = 0; h < 2; ++h) {
                const int row = row0 + wm * 64 + f * 16 + h * 8 + (l >> 2);
                const float s = 1.0f / 268435456.0f;   // 2^-28
                *(float2*)(Cout + (size_t)row * DIM_ + nb) =
                    make_float2(acc[f][j][2 * h] * s, acc[f][j][2 * h + 1] * s);
            }
        }
    }
}

// ---------------- host ------------------------------------------------------
extern "C" void kernel_launch(void* const* d_in, const int* in_sizes, int n_in,
                              void* d_out, int out_size)
{
    const float* x  = (const float*)d_in[0];
    const float* Pi = (const float*)d_in[1];
    const float* cb = (const float*)d_in[2];
    float* out = (float*)d_out;

    unsigned short *x0, *x1, *p0, *p1, *th, *yh;
    cudaGetSymbolAddress((void**)&x0, g_x0);
    cudaGetSymbolAddress((void**)&x1, g_x1);
    cudaGetSymbolAddress((void**)&p0, g_p0);
    cudaGetSymbolAddress((void**)&p1, g_p1);
    cudaGetSymbolAddress((void**)&th, g_th);
    cudaGetSymbolAddress((void**)&yh, g_yh);

    const size_t N = (size_t)DIM_ * DIM_;
    const int smem1 = NSTG1G1 * STG1B;  // 98304 (x2 CTAs/SM = 196608)
    const int smem2 = NSTG2 * STG2B;    // 98304
    cudaFuncSetAttribute(gemm1_kernel,
                         cudaFuncAttributeMaxDynamicSharedMemorySize, smem1);
    cudaFuncSetAttribute(gemm2_kernel,
                         cudaFuncAttributeMaxDynamicSharedMemorySize, smem2);

    // 1) prep: 2^12 x -> (x0,x1) ; 2^16 Pi -> (p0,p1) ; fp16(2^16 Pi^T) -> th
    split2_kernel<4096><<<(int)(N / 4 / 256), 256>>>((const float4*)x,
                                                     (uint32_t*)x0, (uint32_t*)x1);
    split2_kernel<65536><<<(int)(N / 4 / 256), 256>>>((const float4*)Pi,
                                                      (uint32_t*)p0, (uint32_t*)p1);
    transhalf_kernel<<<dim3(DIM_ / 32, DIM_ / 32), dim3(32, 8)>>>(Pi, th);

    // 2) GEMM1 (3-product, CTA 128x64, 2 CTAs/SM, 32x32 warp tiles) -> yh
    dim3 grid1(DIM_ / BN1, DIM_ / BM);
    gemm1_kernel<<<grid1, 256, smem1>>>(x0, x1, p0, p1, cb, yh);
    // 3) GEMM2 (single product, CTA 128x128): out = (2^12 y~ @ 2^16 Pi) * 2^-28
    dim3 grid2(DIM_ / BN, DIM_ / BM);
    gemm2_kernel<<<grid2, 256, smem2>>>(yh, th, out);
}

// round 17
// speedup vs baseline: 2.1599x; 1.0229x over previous
#include <cuda_runtime.h>
#include <cuda_fp16.h>
#include <cstdint>

#define DIM_ 4096
#define BM 128
#define BN1 64            // CTA tile N for both GEMMs (2 CTAs/SM config)

// ---- shared geometry: BKH=64, 128B rows, XOR-swizzled ----------------------
#define BKH1 64
#define NCH1 (DIM_ / BKH1)    // 64 chunks
#define GRP1 2                // GEMM1: drain every 2 chunks = 128 k
#define TILE1B (BM * 128)     // 16384 B (128-row tile)
#define TILEB1B (BN1 * 128)   // 8192 B  (64-row tile)
#define STG1B (2 * TILE1B + 2 * TILEB1B)  // GEMM1 stage: A0,A1,B0,B1 = 49152 B
#define NSTG1G1 2             // GEMM1: 2 stages (2 CTAs/SM)
#define STG2B (TILE1B + TILEB1B)          // GEMM2 stage: A,B = 24576 B
#define NSTG2 3

// Scales (exact powers of 2): x*2^12 -> (x0,x1); Pi*2^16 -> (p0,p1);
// y~ stored fp16(c*2^12); Pi^T stored fp16(Pi^T*2^16).
// GEMM1 acc = 2^28*y, bnd*2^27. GEMM2 acc = 2^28*x~, out *2^-28.

// ---------------- scratch (allocation-free rule: __device__ globals) --------
__device__ unsigned short g_x0[(size_t)DIM_ * DIM_];
__device__ unsigned short g_x1[(size_t)DIM_ * DIM_];
__device__ unsigned short g_p0[(size_t)DIM_ * DIM_];
__device__ unsigned short g_p1[(size_t)DIM_ * DIM_];
__device__ unsigned short g_th[(size_t)DIM_ * DIM_];   // fp16(2^16 Pi^T), K-major
__device__ unsigned short g_yh[(size_t)DIM_ * DIM_];   // fp16(2^12 y~)

// ---------------- PTX helpers -----------------------------------------------
__device__ __forceinline__ uint32_t smem_u32(const void* p) {
    uint32_t a;
    asm("{ .reg .u64 t; cvta.to.shared.u64 t, %1; cvt.u32.u64 %0, t; }" : "=r"(a) : "l"(p));
    return a;
}
__device__ __forceinline__ void cpasync16(uint32_t sa, const void* g) {
    asm volatile("cp.async.cg.shared.global [%0], [%1], 16;" :: "r"(sa), "l"(g));
}
__device__ __forceinline__ void ldsm4(uint32_t* r, uint32_t a) {
    asm volatile("ldmatrix.sync.aligned.m8n8.x4.shared.b16 {%0,%1,%2,%3}, [%4];"
                 : "=r"(r[0]), "=r"(r[1]), "=r"(r[2]), "=r"(r[3]) : "r"(a));
}
__device__ __forceinline__ void mma16816(float* d, const uint32_t* a, const uint32_t* b) {
    asm volatile("mma.sync.aligned.m16n8k16.row.col.f32.f16.f16.f32 "
                 "{%0,%1,%2,%3}, {%4,%5,%6,%7}, {%8,%9}, {%0,%1,%2,%3};"
                 : "+f"(d[0]), "+f"(d[1]), "+f"(d[2]), "+f"(d[3])
                 : "r"(a[0]), "r"(a[1]), "r"(a[2]), "r"(a[3]), "r"(b[0]), "r"(b[1]));
}
#define CP_COMMIT() asm volatile("cp.async.commit_group;" ::: "memory")
#define CP_WAIT1()  asm volatile("cp.async.wait_group 1;" ::: "memory")

// ---------------- fp16 2-split (Markidis, pre-scaled) -----------------------
__device__ __forceinline__ void hsplit2(float v, unsigned short& b0, unsigned short& b1) {
    __half h0 = __float2half_rn(v);
    float r = v - __half2float(h0);
    __half h1 = __float2half_rn(r);
    b0 = *reinterpret_cast<unsigned short*>(&h0);
    b1 = *reinterpret_cast<unsigned short*>(&h1);
}

template<int SCALE>
__global__ void split2_kernel(const float4* __restrict__ in,
                              uint32_t* __restrict__ o0, uint32_t* __restrict__ o1) {
    int i = blockIdx.x * blockDim.x + threadIdx.x;
    float4 v = in[i];
    const float s = (float)SCALE;
    unsigned short a0[4], a1[4];
    hsplit2(v.x * s, a0[0], a1[0]);
    hsplit2(v.y * s, a0[1], a1[1]);
    hsplit2(v.z * s, a0[2], a1[2]);
    hsplit2(v.w * s, a0[3], a1[3]);
    o0[2 * i] = a0[0] | ((uint32_t)a0[1] << 16); o0[2 * i + 1] = a0[2] | ((uint32_t)a0[3] << 16);
    o1[2 * i] = a1[0] | ((uint32_t)a1[1] << 16); o1[2 * i + 1] = a1[2] | ((uint32_t)a1[3] << 16);
}

// Fused Pi prep: one read of Pi -> (p0,p1) split row-major + th transposed fp16
__global__ void piprep_kernel(const float* __restrict__ Pi,
                              unsigned short* __restrict__ p0,
                              unsigned short* __restrict__ p1,
                              unsigned short* __restrict__ th) {
    __shared__ float tile[32][33];
    int tx = threadIdx.x, ty = threadIdx.y;
    int c0 = blockIdx.x * 32, r0 = blockIdx.y * 32;
    #pragma unroll
    for (int i = 0; i < 4; ++i) {
        const size_t o = (size_t)(r0 + ty + 8 * i) * DIM_ + c0 + tx;
        const float v = Pi[o];
        tile[ty + 8 * i][tx] = v;
        unsigned short b0, b1;
        hsplit2(v * 65536.0f, b0, b1);
        p0[o] = b0;
        p1[o] = b1;
    }
    __syncthreads();
    #pragma unroll
    for (int i = 0; i < 4; ++i) {
        __half h = __float2half_rn(tile[tx][ty + 8 * i] * 65536.0f);
        th[(size_t)(c0 + ty + 8 * i) * DIM_ + r0 + tx] = *reinterpret_cast<unsigned short*>(&h);
    }
}

// ---------------- GEMM1: 3-product split HMMA + quantize (unchanged R15) ----
__global__ __launch_bounds__(256, 2)
void gemm1_kernel(const unsigned short* __restrict__ A0, const unsigned short* __restrict__ A1,
                  const unsigned short* __restrict__ Bm0, const unsigned short* __restrict__ Bm1,
                  const float* __restrict__ cb, unsigned short* __restrict__ Yh)
{
    extern __shared__ char smem[];
    const uint32_t sb = smem_u32(smem);
    __shared__ float s_bnd[15];        // 2^27 * (c_i + c_{i+1})
    __shared__ uint32_t s_cbh[16];     // fp16(2^12 * codebook), low 16 bits

    const int tid = threadIdx.x;
    const int w = tid >> 5, l = tid & 31;
    const int wm = w & 3, wn = w >> 2;          // 4x2 warp grid, warp tile 32x32
    const int row0 = blockIdx.y * BM;
    const int col0 = blockIdx.x * BN1;

    if (tid < 16) {
        __half h = __float2half_rn(cb[tid] * 4096.0f);
        s_cbh[tid] = (uint32_t)(*reinterpret_cast<unsigned short*>(&h));
    }
    if (tid < 15) s_bnd[tid] = (cb[tid] + cb[tid + 1]) * 134217728.0f;  // 2^27

    const unsigned short* abase[2] = {A0 + (size_t)row0 * DIM_, A1 + (size_t)row0 * DIM_};
    const unsigned short* bbase[2] = {Bm0 + (size_t)col0 * DIM_, Bm1 + (size_t)col0 * DIM_};

    uint32_t goffA[4], soffA[4], goffB[2], soffB[2];
    #pragma unroll
    for (int i = 0; i < 4; ++i) {
        const int id = i * 256 + tid;
        const int r = id >> 3, c = id & 7;
        goffA[i] = (uint32_t)(r * DIM_ + c * 8);
        soffA[i] = (uint32_t)(r * 128 + ((c ^ (r & 7)) * 16));
    }
    #pragma unroll
    for (int i = 0; i < 2; ++i) {
        const int id = i * 256 + tid;
        const int r = id >> 3, c = id & 7;
        goffB[i] = (uint32_t)(r * DIM_ + c * 8);
        soffB[i] = (uint32_t)(r * 128 + ((c ^ (r & 7)) * 16));
    }

    auto load_chunk = [&](int ch, int st) {
        const int k0 = ch * BKH1;
        const uint32_t stg = sb + st * STG1B;
        #pragma unroll
        for (int t = 0; t < 2; ++t)
            #pragma unroll
            for (int i = 0; i < 4; ++i)
                cpasync16(stg + t * TILE1B + soffA[i], abase[t] + goffA[i] + k0);
        #pragma unroll
        for (int t = 0; t < 2; ++t)
            #pragma unroll
            for (int i = 0; i < 2; ++i)
                cpasync16(stg + 2 * TILE1B + t * TILEB1B + soffB[i], bbase[t] + goffB[i] + k0);
        CP_COMMIT();
    };

    float acc[2][4][4];     // RZ-chained partials (reset every GRP1 chunks)
    float racc[2][4][4];    // RN register totals
    #pragma unroll
    for (int f = 0; f < 2; ++f)
        #pragma unroll
        for (int j = 0; j < 4; ++j)
            #pragma unroll
            for (int q = 0; q < 4; ++q) { acc[f][j][q] = 0.0f; racc[f][j][q] = 0.0f; }

    const int lxor = l & 7;
    const int a_row = wm * 32 + (l & 15);
    const int a_c0  = l >> 4;
    const int b_row = wn * 32 + (l & 7) + ((l >> 4) & 1) * 8;
    const int b_c0  = (l >> 3) & 1;

    load_chunk(0, 0);

    for (int t = 0; t < NCH1; ++t) {
        __syncthreads();                 // overwrite target (stage (t+1)&1) free
        if (t + 1 < NCH1) load_chunk(t + 1, (t + 1) & 1);
        else              CP_COMMIT();   // empty group keeps pending-count exact
        CP_WAIT1();                      // group t complete
        __syncthreads();                 // visibility of stage t to all warps

        const uint32_t base = sb + (t & 1) * STG1B;
        #pragma unroll
        for (int ks = 0; ks < 4; ++ks) {
            uint32_t afr[2][2][4];
            #pragma unroll
            for (int s = 0; s < 2; ++s)
                #pragma unroll
                for (int f = 0; f < 2; ++f)
                    ldsm4(afr[s][f], base + s * TILE1B
                          + (a_row + f * 16) * 128 + (((a_c0 + 2 * ks) ^ lxor) * 16));

            #pragma unroll
            for (int sB = 0; sB < 2; ++sB) {
                uint32_t bfr[2][4];
                #pragma unroll
                for (int p = 0; p < 2; ++p)
                    ldsm4(bfr[p], base + 2 * TILE1B + sB * TILEB1B
                          + (b_row + p * 16) * 128 + (((b_c0 + 2 * ks) ^ lxor) * 16));
                // sB==0: a0*b0 + a1*b0 ; sB==1: a0*b1
                #pragma unroll
                for (int f = 0; f < 2; ++f)
                    #pragma unroll
                    for (int j = 0; j < 4; ++j)
                        mma16816(acc[f][j], afr[0][f], &bfr[j >> 1][(j & 1) * 2]);
                if (sB == 0) {
                    #pragma unroll
                    for (int f = 0; f < 2; ++f)
                        #pragma unroll
                        for (int j = 0; j < 4; ++j)
                            mma16816(acc[f][j], afr[1][f], &bfr[j >> 1][(j & 1) * 2]);
                }
            }
        }

        if ((t & (GRP1 - 1)) == (GRP1 - 1)) {
            #pragma unroll
            for (int f = 0; f < 2; ++f)
                #pragma unroll
                for (int j = 0; j < 4; ++j)
                    #pragma unroll
                    for (int q = 0; q < 4; ++q) {
                        racc[f][j][q] += acc[f][j][q];
                        acc[f][j][q] = 0.0f;
                    }
        }
    }

    // ---- epilogue: quantize -> single fp16 y~ -------------------------------
    #pragma unroll
    for (int f = 0; f < 2; ++f) {
        #pragma unroll
        for (int j = 0; j < 4; ++j) {
            const int nb = col0 + wn * 32 + j * 8 + (l & 3) * 2;
            #pragma unroll
            for (int h = 0; h < 2; ++h) {
                const int row = row0 + wm * 32 + f * 16 + h * 8 + (l >> 2);
                const float va = racc[f][j][2 * h];
                const float vb = racc[f][j][2 * h + 1];
                int ia = 0, ib = 0;
                #pragma unroll
                for (int q = 0; q < 15; ++q) {
                    ia += (va > s_bnd[q]) ? 1 : 0;
                    ib += (vb > s_bnd[q]) ? 1 : 0;
                }
                const size_t o = ((size_t)row * DIM_ + nb) >> 1;
                ((uint32_t*)Yh)[o] = s_cbh[ia] | (s_cbh[ib] << 16);
            }
        }
    }
}

// ---------------- GEMM2: single-product fp16 HMMA, 2 CTAs/SM ----------------
// 256 threads, 4x2 warp grid (32x32 warp tiles), CTA tile 128x64, 3-stage.
__global__ __launch_bounds__(256, 2)
void gemm2_kernel(const unsigned short* __restrict__ A, const unsigned short* __restrict__ B,
                  float* __restrict__ Cout)
{
    extern __shared__ char smem[];
    const uint32_t sb = smem_u32(smem);

    const int tid = threadIdx.x;
    const int w = tid >> 5, l = tid & 31;
    const int wm = w & 3, wn = w >> 2;          // 4x2 warp grid, warp tile 32x32
    const int row0 = blockIdx.y * BM;
    const int col0 = blockIdx.x * BN1;

    const unsigned short* abase = A + (size_t)row0 * DIM_;
    const unsigned short* bbase = B + (size_t)col0 * DIM_;

    uint32_t goffA[4], soffA[4], goffB[2], soffB[2];
    #pragma unroll
    for (int i = 0; i < 4; ++i) {
        const int id = i * 256 + tid;
        const int r = id >> 3, c = id & 7;
        goffA[i] = (uint32_t)(r * DIM_ + c * 8);
        soffA[i] = (uint32_t)(r * 128 + ((c ^ (r & 7)) * 16));
    }
    #pragma unroll
    for (int i = 0; i < 2; ++i) {
        const int id = i * 256 + tid;
        const int r = id >> 3, c = id & 7;
        goffB[i] = (uint32_t)(r * DIM_ + c * 8);
        soffB[i] = (uint32_t)(r * 128 + ((c ^ (r & 7)) * 16));
    }

    auto load_chunk = [&](int ch, int st) {
        const int k0 = ch * BKH1;
        const uint32_t stg = sb + st * STG2B;
        #pragma unroll
        for (int i = 0; i < 4; ++i)
            cpasync16(stg + soffA[i], abase + goffA[i] + k0);
        #pragma unroll
        for (int i = 0; i < 2; ++i)
            cpasync16(stg + TILE1B + soffB[i], bbase + goffB[i] + k0);
        CP_COMMIT();
    };

    float acc[2][4][4];
    #pragma unroll
    for (int f = 0; f < 2; ++f)
        #pragma unroll
        for (int j = 0; j < 4; ++j)
            #pragma unroll
            for (int q = 0; q < 4; ++q) acc[f][j][q] = 0.0f;

    const int lxor = l & 7;
    const int a_row = wm * 32 + (l & 15);
    const int a_c0  = l >> 4;
    const int b_row = wn * 32 + (l & 7) + ((l >> 4) & 1) * 8;
    const int b_c0  = (l >> 3) & 1;

    load_chunk(0, 0);
    load_chunk(1, 1);

    for (int t = 0; t < NCH1; ++t) {
        const int st = t % 3;
        CP_WAIT1();
        __syncthreads();
        if (t + 2 < NCH1) load_chunk(t + 2, (t + 2) % 3);
        else              CP_COMMIT();

        const uint32_t base = sb + st * STG2B;
        #pragma unroll
        for (int ks = 0; ks < 4; ++ks) {
            uint32_t afr[2][4];
            #pragma unroll
            for (int f = 0; f < 2; ++f)
                ldsm4(afr[f], base
                      + (a_row + f * 16) * 128 + (((a_c0 + 2 * ks) ^ lxor) * 16));
            uint32_t bfr[2][4];
            #pragma unroll
            for (int p = 0; p < 2; ++p)
                ldsm4(bfr[p], base + TILE1B
                      + (b_row + p * 16) * 128 + (((b_c0 + 2 * ks) ^ lxor) * 16));
            #pragma unroll
            for (int f = 0; f < 2; ++f)
                #pragma unroll
                for (int j = 0; j < 4; ++j)
                    mma16816(acc[f][j], afr[f], &bfr[j >> 1][(j & 1) * 2]);
        }
    }

    // ---- epilogue: out = acc * 2^-28 ---------------------------------------
    #pragma unroll
    for (int f = 0; f < 2; ++f) {
        #pragma unroll
        for (int j = 0; j < 4; ++j) {
            const int nb = col0 + wn * 32 + j * 8 + (l & 3) * 2;
            #pragma unroll
            for (int h = 0; h < 2; ++h) {
                const int row = row0 + wm * 32 + f * 16 + h * 8 + (l >> 2);
                const float s = 1.0f / 268435456.0f;   // 2^-28
                *(float2*)(Cout + (size_t)row * DIM_ + nb) =
                    make_float2(acc[f][j][2 * h] * s, acc[f][j][2 * h + 1] * s);
            }
        }
    }
}

// ---------------- host ------------------------------------------------------
extern "C" void kernel_launch(void* const* d_in, const int* in_sizes, int n_in,
                              void* d_out, int out_size)
{
    const float* x  = (const float*)d_in[0];
    const float* Pi = (const float*)d_in[1];
    const float* cb = (const float*)d_in[2];
    float* out = (float*)d_out;

    unsigned short *x0, *x1, *p0, *p1, *th, *yh;
    cudaGetSymbolAddress((void**)&x0, g_x0);
    cudaGetSymbolAddress((void**)&x1, g_x1);
    cudaGetSymbolAddress((void**)&p0, g_p0);
    cudaGetSymbolAddress((void**)&p1, g_p1);
    cudaGetSymbolAddress((void**)&th, g_th);
    cudaGetSymbolAddress((void**)&yh, g_yh);

    const size_t N = (size_t)DIM_ * DIM_;
    const int smem1 = NSTG1G1 * STG1B;  // 98304 (x2 CTAs/SM = 196608)
    const int smem2 = NSTG2 * STG2B;    // 73728 (x2 CTAs/SM = 147456)
    cudaFuncSetAttribute(gemm1_kernel,
                         cudaFuncAttributeMaxDynamicSharedMemorySize, smem1);
    cudaFuncSetAttribute(gemm2_kernel,
                         cudaFuncAttributeMaxDynamicSharedMemorySize, smem2);

    // 1) prep: 2^12 x -> (x0,x1) ; fused Pi prep: (p0,p1) + th in one pass
    split2_kernel<4096><<<(int)(N / 4 / 256), 256>>>((const float4*)x,
                                                     (uint32_t*)x0, (uint32_t*)x1);
    piprep_kernel<<<dim3(DIM_ / 32, DIM_ / 32), dim3(32, 8)>>>(Pi, p0, p1, th);

    // 2) GEMM1 (3-product, CTA 128x64, 2 CTAs/SM, 32x32 warp tiles) -> yh
    dim3 grid1(DIM_ / BN1, DIM_ / BM);
    gemm1_kernel<<<grid1, 256, smem1>>>(x0, x1, p0, p1, cb, yh);
    // 3) GEMM2 (single product, CTA 128x64, 2 CTAs/SM): out = y~ @ Pi * 2^-28
    gemm2_kernel<<<grid1, 256, smem2>>>(yh, th, out);
}